// round 6
// baseline (speedup 1.0000x reference)
#include <cuda_runtime.h>
#include <cuda_bf16.h>
#include <math.h>
#include <stdint.h>

#define Bb 2
#define Ss 2048
#define Hh 2048
#define NHh 16
#define HDd 128
#define Mm (Bb*Ss)
#define GK 2048            // real K
#define GCH 32             // k per pipeline chunk
#define GNCH (GK/GCH)      // 64

// ---------------- scratch ----------------
__device__ float g_q[(size_t)Bb*NHh*Ss*HDd];
__device__ float g_k[(size_t)Bb*NHh*Ss*HDd];
__device__ float g_v[(size_t)Bb*NHh*Ss*HDd];
__device__ float g_o[(size_t)Bb*Ss*Hh];
__device__ float g_cos[Ss*64];
__device__ float g_sin[Ss*64];
__device__ __nv_bfloat16 g_ah[(size_t)Mm*GK];    // activation hi
__device__ __nv_bfloat16 g_al[(size_t)Mm*GK];    // activation lo
__device__ __nv_bfloat16 g_wh[3][(size_t)Hh*GK]; // weight hi (q,k,v / o reuses [0])
__device__ __nv_bfloat16 g_wl[3][(size_t)Hh*GK]; // weight lo
// flash bf16 operands (hi/lo split)
__device__ __nv_bfloat16 g_qh[(size_t)Bb*NHh*Ss*HDd];
__device__ __nv_bfloat16 g_ql[(size_t)Bb*NHh*Ss*HDd];
__device__ __nv_bfloat16 g_kh[(size_t)Bb*NHh*Ss*HDd];
__device__ __nv_bfloat16 g_kl[(size_t)Bb*NHh*Ss*HDd];
__device__ __nv_bfloat16 g_vh[(size_t)Bb*NHh*Ss*HDd];
__device__ __nv_bfloat16 g_vl[(size_t)Bb*NHh*Ss*HDd];

// ---------------- PTX helpers ----------------
__device__ __forceinline__ uint32_t smem_u32(const void* p) {
    uint32_t a;
    asm("{ .reg .u64 t; cvta.to.shared.u64 t, %1; cvt.u32.u64 %0, t; }" : "=r"(a) : "l"(p));
    return a;
}
#define CP_ASYNC16(sa, gp) \
    asm volatile("cp.async.cg.shared.global [%0], [%1], 16;" :: "r"(sa), "l"(gp) : "memory")
#define CP_COMMIT() asm volatile("cp.async.commit_group;" ::: "memory")
#define CP_WAIT0()  asm volatile("cp.async.wait_group 0;" ::: "memory")
#define CP_WAIT1()  asm volatile("cp.async.wait_group 1;" ::: "memory")
#define CP_WAIT2()  asm volatile("cp.async.wait_group 2;" ::: "memory")

__device__ __forceinline__ void ldsm_x4(uint32_t* r, uint32_t addr) {
    asm volatile("ldmatrix.sync.aligned.m8n8.x4.shared.b16 {%0,%1,%2,%3}, [%4];"
        : "=r"(r[0]), "=r"(r[1]), "=r"(r[2]), "=r"(r[3]) : "r"(addr));
}
__device__ __forceinline__ void ldsm_x4_t(uint32_t* r, uint32_t addr) {
    asm volatile("ldmatrix.sync.aligned.m8n8.x4.trans.shared.b16 {%0,%1,%2,%3}, [%4];"
        : "=r"(r[0]), "=r"(r[1]), "=r"(r[2]), "=r"(r[3]) : "r"(addr));
}
__device__ __forceinline__ void mma16816(float* d, const uint32_t* a, const uint32_t* b) {
    asm volatile("mma.sync.aligned.m16n8k16.row.col.f32.bf16.bf16.f32 "
        "{%0,%1,%2,%3}, {%4,%5,%6,%7}, {%8,%9}, {%0,%1,%2,%3};"
        : "+f"(d[0]), "+f"(d[1]), "+f"(d[2]), "+f"(d[3])
        : "r"(a[0]), "r"(a[1]), "r"(a[2]), "r"(a[3]), "r"(b[0]), "r"(b[1]));
}
#define SWZ32(o) ((o) ^ (((o) >> 3) & 0x30))   // 64B-row swizzle (Swizzle<2,4,3>)

// ---------------- hi/lo pair split ----------------
__global__ void split_pair_kernel(const float* __restrict__ X,
                                  __nv_bfloat16* __restrict__ Xh,
                                  __nv_bfloat16* __restrict__ Xl, int n)
{
    int idx = blockIdx.x * blockDim.x + threadIdx.x;
    if (idx >= n) return;
    float x = X[idx];
    __nv_bfloat16 hi = __float2bfloat16(x);
    Xh[idx] = hi;
    Xl[idx] = __float2bfloat16(x - __bfloat162float(hi));
}

// ---------------- HMMA GEMM v3: CTA 256x128, 8 warps 64x64, 4-stage, hi/lo reuse
// C = Ah*Bh^T + Al*Bh^T + Ah*Bl^T   (A [M,K] hi/lo, B [N,K] hi/lo)
// MODE 0: row-major [M,N]; MODE 1: head scatter.
#define STG 49152u
#define AhO 0u
#define AlO 16384u
#define BhO 32768u
#define BlO 40960u

template <int MODE>
__global__ __launch_bounds__(256, 1) void gemm3(const __nv_bfloat16* __restrict__ Ah,
                                                const __nv_bfloat16* __restrict__ Al,
                                                const __nv_bfloat16* __restrict__ Bh,
                                                const __nv_bfloat16* __restrict__ Bl,
                                                float* __restrict__ C)
{
    extern __shared__ char smem[];
    const uint32_t sb = smem_u32(smem);
    const int tid = threadIdx.x;
    const int wid = tid >> 5;
    const int lane = tid & 31;
    const int n0 = blockIdx.x * 128;
    const int m0 = blockIdx.y * 256;
    const int wm = wid & 3;      // 4 warps along M (64 rows each)
    const int wn = wid >> 2;     // 2 warps along N (64 cols each)

    float acc[4][8][4];
#pragma unroll
    for (int mi = 0; mi < 4; mi++)
#pragma unroll
        for (int ni = 0; ni < 8; ni++)
#pragma unroll
            for (int q = 0; q < 4; q++) acc[mi][ni][q] = 0.f;

#define LOAD_STAGE(ci, st) do {                                                     \
    const int _k0 = (ci) * GCH;                                                     \
    const uint32_t _bs = sb + (uint32_t)(st) * STG;                                 \
    _Pragma("unroll")                                                               \
    for (int _i = 0; _i < 4; _i++) {                                                \
        int _idx = tid + 256 * _i;                                                  \
        int _r = _idx >> 2;                                                         \
        int _cb = (_idx & 3) * 16;                                                  \
        CP_ASYNC16(_bs + AhO + SWZ32(_r * 64 + _cb),                                \
                   Ah + (size_t)(m0 + _r) * GK + _k0 + (_cb >> 1));                 \
    }                                                                               \
    _Pragma("unroll")                                                               \
    for (int _i = 0; _i < 4; _i++) {                                                \
        int _idx = tid + 256 * _i;                                                  \
        int _r = _idx >> 2;                                                         \
        int _cb = (_idx & 3) * 16;                                                  \
        CP_ASYNC16(_bs + AlO + SWZ32(_r * 64 + _cb),                                \
                   Al + (size_t)(m0 + _r) * GK + _k0 + (_cb >> 1));                 \
    }                                                                               \
    _Pragma("unroll")                                                               \
    for (int _i = 0; _i < 2; _i++) {                                                \
        int _idx = tid + 256 * _i;                                                  \
        int _r = _idx >> 2;                                                         \
        int _cb = (_idx & 3) * 16;                                                  \
        CP_ASYNC16(_bs + BhO + SWZ32(_r * 64 + _cb),                                \
                   Bh + (size_t)(n0 + _r) * GK + _k0 + (_cb >> 1));                 \
    }                                                                               \
    _Pragma("unroll")                                                               \
    for (int _i = 0; _i < 2; _i++) {                                                \
        int _idx = tid + 256 * _i;                                                  \
        int _r = _idx >> 2;                                                         \
        int _cb = (_idx & 3) * 16;                                                  \
        CP_ASYNC16(_bs + BlO + SWZ32(_r * 64 + _cb),                                \
                   Bl + (size_t)(n0 + _r) * GK + _k0 + (_cb >> 1));                 \
    }                                                                               \
    CP_COMMIT();                                                                    \
} while (0)

    // ldmatrix address components (64B rows)
    const uint32_t a_half = (uint32_t)((lane >> 4) * 16);
    const uint32_t a_xor = (uint32_t)((((lane & 15) >> 1) & 3) * 16);
    uint32_t aRow[4];
#pragma unroll
    for (int mi = 0; mi < 4; mi++)
        aRow[mi] = (uint32_t)((wm * 64 + mi * 16 + (lane & 15)) * 64);

    const int b_lrow = (lane & 7) + ((lane >> 4) << 3);
    const uint32_t b_half = (uint32_t)(((lane >> 3) & 1) * 16);
    const uint32_t b_xor = (uint32_t)((((lane & 7) >> 1) & 3) * 16);
    uint32_t bRow[4];
#pragma unroll
    for (int nt = 0; nt < 4; nt++)
        bRow[nt] = (uint32_t)((wn * 64 + nt * 16 + b_lrow) * 64);

    LOAD_STAGE(0, 0);
    LOAD_STAGE(1, 1);
    LOAD_STAGE(2, 2);

    for (int c = 0; c < GNCH; c++) {
        if (c <= GNCH - 3) CP_WAIT2();
        else if (c == GNCH - 2) CP_WAIT1();
        else CP_WAIT0();
        __syncthreads();
        if (c + 3 < GNCH) LOAD_STAGE(c + 3, (c + 3) & 3);

        const uint32_t bs = sb + (uint32_t)(c & 3) * STG;
#pragma unroll
        for (int kk = 0; kk < 2; kk++) {
            const uint32_t acol = ((uint32_t)(kk * 32) + a_half) ^ a_xor;
            const uint32_t bcol = ((uint32_t)(kk * 32) + b_half) ^ b_xor;
            uint32_t ah4[4][4], bh4[4][4], xx4[4][4];
#pragma unroll
            for (int mi = 0; mi < 4; mi++)
                ldsm_x4(ah4[mi], bs + AhO + aRow[mi] + acol);
#pragma unroll
            for (int nt = 0; nt < 4; nt++)
                ldsm_x4(bh4[nt], bs + BhO + bRow[nt] + bcol);
            // hi*hi
#pragma unroll
            for (int mi = 0; mi < 4; mi++)
#pragma unroll
                for (int nt = 0; nt < 4; nt++) {
                    mma16816(acc[mi][2 * nt],     ah4[mi], bh4[nt]);
                    mma16816(acc[mi][2 * nt + 1], ah4[mi], bh4[nt] + 2);
                }
            // lo*hi
#pragma unroll
            for (int mi = 0; mi < 4; mi++)
                ldsm_x4(xx4[mi], bs + AlO + aRow[mi] + acol);
#pragma unroll
            for (int mi = 0; mi < 4; mi++)
#pragma unroll
                for (int nt = 0; nt < 4; nt++) {
                    mma16816(acc[mi][2 * nt],     xx4[mi], bh4[nt]);
                    mma16816(acc[mi][2 * nt + 1], xx4[mi], bh4[nt] + 2);
                }
            // hi*lo
#pragma unroll
            for (int nt = 0; nt < 4; nt++)
                ldsm_x4(xx4[nt], bs + BlO + bRow[nt] + bcol);
#pragma unroll
            for (int mi = 0; mi < 4; mi++)
#pragma unroll
                for (int nt = 0; nt < 4; nt++) {
                    mma16816(acc[mi][2 * nt],     ah4[mi], xx4[nt]);
                    mma16816(acc[mi][2 * nt + 1], ah4[mi], xx4[nt] + 2);
                }
        }
    }

    // epilogue
    const int er = lane >> 2;
    const int ec = (lane & 3) * 2;
#pragma unroll
    for (int mi = 0; mi < 4; mi++) {
#pragma unroll
        for (int ni = 0; ni < 8; ni++) {
            const int m = m0 + wm * 64 + mi * 16 + er;
            const int n = n0 + wn * 64 + ni * 8 + ec;
            float* dst0;
            float* dst1;
            if (MODE == 0) {
                dst0 = C + (size_t)m * Hh + n;
                dst1 = C + (size_t)(m + 8) * Hh + n;
            } else {
                const int b_ = m >> 11;
                const int s_ = m & (Ss - 1);
                const int h_ = n >> 7;
                const int d_ = n & (HDd - 1);
                dst0 = C + (((size_t)b_ * NHh + h_) * Ss + s_) * HDd + d_;
                dst1 = dst0 + 8 * HDd;
            }
            *(float2*)dst0 = make_float2(acc[mi][ni][0], acc[mi][ni][1]);
            *(float2*)dst1 = make_float2(acc[mi][ni][2], acc[mi][ni][3]);
        }
    }
#undef LOAD_STAGE
}

// ---------------- RoPE tables ----------------
__global__ void rope_tables_kernel()
{
    int idx = blockIdx.x * blockDim.x + threadIdx.x;
    if (idx >= Ss * 64) return;
    int s = idx >> 6;
    int d = idx & 63;
    float invf = (float)pow(10000.0, -(double)d * (1.0 / 64.0));
    float ang = (float)s * invf;
    float c, sn;
    sincosf(ang, &sn, &c);
    g_cos[idx] = c;
    g_sin[idx] = sn;
}

// ---------------- RoPE apply + bf16 hi/lo split (Q scaled by 1/sqrt(HD)) --------
__global__ void rope_split_kernel(const float* __restrict__ q, const float* __restrict__ k,
                                  __nv_bfloat16* __restrict__ qh, __nv_bfloat16* __restrict__ ql,
                                  __nv_bfloat16* __restrict__ kh, __nv_bfloat16* __restrict__ kl)
{
    int idx = blockIdx.x * blockDim.x + threadIdx.x;
    if (idx >= Bb * NHh * Ss * 64) return;
    const int d = idx & 63;
    const int s = (idx >> 6) & (Ss - 1);
    const int bh = idx >> 17;
    const int t = (s << 6) + d;
    const float c = g_cos[t];
    const float sn = g_sin[t];
    const float rscale = 0.08838834764831845f;
    const size_t base = ((size_t)bh * Ss + s) * HDd + d;

    float q1 = q[base], q2 = q[base + 64];
    float r1 = (q1 * c - q2 * sn) * rscale;
    float r2 = (q2 * c + q1 * sn) * rscale;
    __nv_bfloat16 h1 = __float2bfloat16(r1);
    __nv_bfloat16 h2 = __float2bfloat16(r2);
    qh[base] = h1; qh[base + 64] = h2;
    ql[base] = __float2bfloat16(r1 - __bfloat162float(h1));
    ql[base + 64] = __float2bfloat16(r2 - __bfloat162float(h2));

    float k1 = k[base], k2 = k[base + 64];
    float s1 = k1 * c - k2 * sn;
    float s2 = k2 * c + k1 * sn;
    __nv_bfloat16 g1 = __float2bfloat16(s1);
    __nv_bfloat16 g2 = __float2bfloat16(s2);
    kh[base] = g1; kh[base + 64] = g2;
    kl[base] = __float2bfloat16(s1 - __bfloat162float(g1));
    kl[base + 64] = __float2bfloat16(s2 - __bfloat162float(g2));
}

// ---------------- HMMA causal flash attention, BM=128, BN=64 (unchanged R4) -----
#define QsO 0u
#define KsO 65536u
#define VhO 131072u
#define VlO 163840u
#define FLASH_SMEM 196608

__global__ __launch_bounds__(256, 1) void flash_mma(
    const __nv_bfloat16* __restrict__ qh, const __nv_bfloat16* __restrict__ ql,
    const __nv_bfloat16* __restrict__ kh, const __nv_bfloat16* __restrict__ kl,
    const __nv_bfloat16* __restrict__ vh, const __nv_bfloat16* __restrict__ vl,
    float* __restrict__ O)
{
    extern __shared__ char smem[];
    const uint32_t sb = smem_u32(smem);
    const int tid = threadIdx.x;
    const int lane = tid & 31;
    const int w = tid >> 5;
    const int qb = (gridDim.x - 1) - blockIdx.x;
    const int bh = blockIdx.y;
    const int b = bh >> 4, h = bh & 15;
    const int qlo = qb * 128;
    const int wr = w * 16;

#pragma unroll
    for (int i = 0; i < 16; i++) {
        int idx = tid + 256 * i;
        int row = idx >> 5;
        int off = (idx & 31) * 16;
        const __nv_bfloat16* src = (off < 256)
            ? qh + ((size_t)bh * Ss + qlo + row) * HDd + (off >> 1)
            : ql + ((size_t)bh * Ss + qlo + row) * HDd + ((off - 256) >> 1);
        uint32_t dst = sb + QsO + row * 512 + (off & ~127) + ((off & 127) ^ ((row & 7) << 4));
        CP_ASYNC16(dst, src);
    }
    CP_COMMIT();

#define LOAD_KV(kb_, s_) do {                                                        \
    const int _klo = (kb_) * 64;                                                     \
    _Pragma("unroll")                                                                \
    for (int _i = 0; _i < 8; _i++) {                                                 \
        int _idx = tid + 256 * _i;                                                   \
        int _row = _idx >> 5;                                                        \
        int _off = (_idx & 31) * 16;                                                 \
        const __nv_bfloat16* _src = (_off < 256)                                     \
            ? kh + ((size_t)bh * Ss + _klo + _row) * HDd + (_off >> 1)               \
            : kl + ((size_t)bh * Ss + _klo + _row) * HDd + ((_off - 256) >> 1);      \
        uint32_t _dst = sb + KsO + (s_) * 32768u + _row * 512 + (_off & ~127)        \
                        + ((_off & 127) ^ ((_row & 7) << 4));                        \
        CP_ASYNC16(_dst, _src);                                                      \
    }                                                                                \
    _Pragma("unroll")                                                                \
    for (int _i = 0; _i < 4; _i++) {                                                 \
        int _idx = tid + 256 * _i;                                                   \
        int _row = _idx >> 4;                                                        \
        int _off = (_idx & 15) * 16;                                                 \
        const __nv_bfloat16* _src = vh + ((size_t)bh * Ss + _klo + _row) * HDd + (_off >> 1); \
        uint32_t _dst = sb + VhO + (s_) * 16384u + _row * 256 + (_off & ~127)        \
                        + ((_off & 127) ^ ((_row & 7) << 4));                        \
        CP_ASYNC16(_dst, _src);                                                      \
    }                                                                                \
    _Pragma("unroll")                                                                \
    for (int _i = 0; _i < 4; _i++) {                                                 \
        int _idx = tid + 256 * _i;                                                   \
        int _row = _idx >> 4;                                                        \
        int _off = (_idx & 15) * 16;                                                 \
        const __nv_bfloat16* _src = vl + ((size_t)bh * Ss + _klo + _row) * HDd + (_off >> 1); \
        uint32_t _dst = sb + VlO + (s_) * 16384u + _row * 256 + (_off & ~127)        \
                        + ((_off & 127) ^ ((_row & 7) << 4));                        \
        CP_ASYNC16(_dst, _src);                                                      \
    }                                                                                \
    CP_COMMIT();                                                                     \
} while (0)

    LOAD_KV(0, 0);

    const int a_row = wr + (lane & 15);
    const uint32_t a_base = sb + QsO + a_row * 512;
    const uint32_t a_half = (uint32_t)((lane >> 4) * 16);
    const uint32_t a_xor = (uint32_t)((a_row & 7) * 16);

    const int b_rowk = (lane & 7) + ((lane >> 4) << 3);
    const uint32_t b_halfk = (uint32_t)(((lane >> 3) & 1) * 16);
    const uint32_t b_xork = (uint32_t)((lane & 7) * 16);

    const int v_row = (lane & 7) + (((lane >> 3) & 1) << 3);
    const uint32_t v_half = (uint32_t)((lane >> 4) * 16);
    const uint32_t v_xor = (uint32_t)((lane & 7) * 16);

    float oacc[16][4];
#pragma unroll
    for (int i = 0; i < 16; i++)
#pragma unroll
        for (int q = 0; q < 4; q++) oacc[i][q] = 0.f;
    float m0 = -1e30f, m1 = -1e30f, l0 = 0.f, l1 = 0.f;

    const int row_q0 = qlo + wr + (lane >> 2);
    const int nkb = 2 * qb + 2;

    for (int kb = 0; kb < nkb; kb++) {
        const int klo = kb * 64;
        CP_WAIT0();
        __syncthreads();
        if (kb + 1 < nkb) LOAD_KV(kb + 1, (kb + 1) & 1);

        const bool warp_skip = (klo > qlo + wr + 15);
        if (!warp_skip) {
            const uint32_t kbase = sb + KsO + (uint32_t)(kb & 1) * 32768u;
            const uint32_t vhb = sb + VhO + (uint32_t)(kb & 1) * 16384u;
            const uint32_t vlb = sb + VlO + (uint32_t)(kb & 1) * 16384u;

            float sacc[8][4];
#pragma unroll
            for (int i = 0; i < 8; i++)
#pragma unroll
                for (int q = 0; q < 4; q++) sacc[i][q] = 0.f;

#pragma unroll
            for (int kk = 0; kk < 8; kk++) {
                const uint32_t acol = ((uint32_t)((kk & 3) * 32) + a_half) ^ a_xor;
                const uint32_t achunk = (uint32_t)((kk >> 2) * 128);
                uint32_t ahi[4], alo[4];
                ldsm_x4(ahi, a_base + achunk + acol);
                ldsm_x4(alo, a_base + 256u + achunk + acol);
                const uint32_t bcol = ((uint32_t)((kk & 3) * 32) + b_halfk) ^ b_xork;
#pragma unroll
                for (int g = 0; g < 4; g++) {
                    uint32_t bk[4];
                    ldsm_x4(bk, kbase + (uint32_t)((g * 16 + b_rowk) * 512) + achunk + bcol);
                    mma16816(sacc[2 * g],     ahi, bk);
                    mma16816(sacc[2 * g + 1], ahi, bk + 2);
                    mma16816(sacc[2 * g],     alo, bk);
                    mma16816(sacc[2 * g + 1], alo, bk + 2);
                }
            }
#pragma unroll
            for (int kk = 0; kk < 8; kk++) {
                const uint32_t acol = ((uint32_t)((kk & 3) * 32) + a_half) ^ a_xor;
                const uint32_t achunk = (uint32_t)((kk >> 2) * 128);
                uint32_t ahi[4];
                ldsm_x4(ahi, a_base + achunk + acol);
                const uint32_t bcol = ((uint32_t)((kk & 3) * 32) + b_halfk) ^ b_xork;
#pragma unroll
                for (int g = 0; g < 4; g++) {
                    uint32_t bk[4];
                    ldsm_x4(bk, kbase + 256u + (uint32_t)((g * 16 + b_rowk) * 512) + achunk + bcol);
                    mma16816(sacc[2 * g],     ahi, bk);
                    mma16816(sacc[2 * g + 1], ahi, bk + 2);
                }
            }

            if (klo + 63 > qlo + wr) {
#pragma unroll
                for (int nt = 0; nt < 8; nt++) {
                    const int cb = klo + nt * 8 + (lane & 3) * 2;
                    if (cb     > row_q0)     sacc[nt][0] = -1e30f;
                    if (cb + 1 > row_q0)     sacc[nt][1] = -1e30f;
                    if (cb     > row_q0 + 8) sacc[nt][2] = -1e30f;
                    if (cb + 1 > row_q0 + 8) sacc[nt][3] = -1e30f;
                }
            }

            float nm0 = -1e30f, nm1 = -1e30f;
#pragma unroll
            for (int nt = 0; nt < 8; nt++) {
                nm0 = fmaxf(nm0, fmaxf(sacc[nt][0], sacc[nt][1]));
                nm1 = fmaxf(nm1, fmaxf(sacc[nt][2], sacc[nt][3]));
            }
            nm0 = fmaxf(nm0, __shfl_xor_sync(0xffffffffu, nm0, 1));
            nm0 = fmaxf(nm0, __shfl_xor_sync(0xffffffffu, nm0, 2));
            nm1 = fmaxf(nm1, __shfl_xor_sync(0xffffffffu, nm1, 1));
            nm1 = fmaxf(nm1, __shfl_xor_sync(0xffffffffu, nm1, 2));
            nm0 = fmaxf(m0, nm0);
            nm1 = fmaxf(m1, nm1);
            const float alpha0 = __expf(m0 - nm0);
            const float alpha1 = __expf(m1 - nm1);
            m0 = nm0; m1 = nm1;

            uint32_t phi[8][2], plo[8][2];
            float s0 = 0.f, s1 = 0.f;
#pragma unroll
            for (int nt = 0; nt < 8; nt++) {
                float p00 = __expf(sacc[nt][0] - m0);
                float p01 = __expf(sacc[nt][1] - m0);
                float p10 = __expf(sacc[nt][2] - m1);
                float p11 = __expf(sacc[nt][3] - m1);
                s0 += p00 + p01;
                s1 += p10 + p11;
                __nv_bfloat162 h0 = __float22bfloat162_rn(make_float2(p00, p01));
                __nv_bfloat162 h1 = __float22bfloat162_rn(make_float2(p10, p11));
                phi[nt][0] = *(uint32_t*)&h0;
                phi[nt][1] = *(uint32_t*)&h1;
                float2 hf0 = __bfloat1622float2(h0);
                float2 hf1 = __bfloat1622float2(h1);
                __nv_bfloat162 e0 = __float22bfloat162_rn(make_float2(p00 - hf0.x, p01 - hf0.y));
                __nv_bfloat162 e1 = __float22bfloat162_rn(make_float2(p10 - hf1.x, p11 - hf1.y));
                plo[nt][0] = *(uint32_t*)&e0;
                plo[nt][1] = *(uint32_t*)&e1;
            }
            s0 += __shfl_xor_sync(0xffffffffu, s0, 1);
            s0 += __shfl_xor_sync(0xffffffffu, s0, 2);
            s1 += __shfl_xor_sync(0xffffffffu, s1, 1);
            s1 += __shfl_xor_sync(0xffffffffu, s1, 2);
            l0 = l0 * alpha0 + s0;
            l1 = l1 * alpha1 + s1;
#pragma unroll
            for (int dt = 0; dt < 16; dt++) {
                oacc[dt][0] *= alpha0; oacc[dt][1] *= alpha0;
                oacc[dt][2] *= alpha1; oacc[dt][3] *= alpha1;
            }

#pragma unroll
            for (int jt = 0; jt < 4; jt++) {
                uint32_t ah[4] = { phi[2 * jt][0], phi[2 * jt][1],
                                   phi[2 * jt + 1][0], phi[2 * jt + 1][1] };
                uint32_t al[4] = { plo[2 * jt][0], plo[2 * jt][1],
                                   plo[2 * jt + 1][0], plo[2 * jt + 1][1] };
                const uint32_t vrow = (uint32_t)((jt * 16 + v_row) * 256);
#pragma unroll
                for (int g = 0; g < 8; g++) {
                    const uint32_t colb = (uint32_t)(g * 32) + v_half;
                    const uint32_t voff = vrow + (colb & ~127u) + ((colb & 127u) ^ v_xor);
                    uint32_t bv[4];
                    ldsm_x4_t(bv, vhb + voff);
                    mma16816(oacc[2 * g],     ah, bv);
                    mma16816(oacc[2 * g + 1], ah, bv + 2);
                    mma16816(oacc[2 * g],     al, bv);
                    mma16816(oacc[2 * g + 1], al, bv + 2);
                }
#pragma unroll
                for (int g = 0; g < 8; g++) {
                    const uint32_t colb = (uint32_t)(g * 32) + v_half;
                    const uint32_t voff = vrow + (colb & ~127u) + ((colb & 127u) ^ v_xor);
                    uint32_t bv[4];
                    ldsm_x4_t(bv, vlb + voff);
                    mma16816(oacc[2 * g],     ah, bv);
                    mma16816(oacc[2 * g + 1], ah, bv + 2);
                }
            }
        }
        __syncthreads();
    }

    const float inv0 = 1.f / l0;
    const float inv1 = 1.f / l1;
    const int col0 = h * HDd + (lane & 3) * 2;
    const size_t base0 = ((size_t)b * Ss + row_q0) * Hh + col0;
    const size_t base1 = ((size_t)b * Ss + row_q0 + 8) * Hh + col0;
#pragma unroll
    for (int dt = 0; dt < 16; dt++) {
        *(float2*)(O + base0 + dt * 8) = make_float2(oacc[dt][0] * inv0, oacc[dt][1] * inv0);
        *(float2*)(O + base1 + dt * 8) = make_float2(oacc[dt][2] * inv1, oacc[dt][3] * inv1);
    }
#undef LOAD_KV
}

// ---------------- launch ----------------
extern "C" void kernel_launch(void* const* d_in, const int* in_sizes, int n_in,
                              void* d_out, int out_size)
{
    (void)in_sizes; (void)n_in; (void)out_size;
    const float* hs = (const float*)d_in[0];
    const float* qw = (const float*)d_in[1];
    const float* kw = (const float*)d_in[2];
    const float* vw = (const float*)d_in[3];
    const float* ow = (const float*)d_in[4];
    float* out = (float*)d_out;

    float *qbuf, *kbuf, *vbuf, *obuf;
    __nv_bfloat16 *ah, *al, *wh, *wl, *qh, *ql, *kh, *kl, *vh, *vl;
    cudaGetSymbolAddress((void**)&qbuf, g_q);
    cudaGetSymbolAddress((void**)&kbuf, g_k);
    cudaGetSymbolAddress((void**)&vbuf, g_v);
    cudaGetSymbolAddress((void**)&obuf, g_o);
    cudaGetSymbolAddress((void**)&ah, g_ah);
    cudaGetSymbolAddress((void**)&al, g_al);
    cudaGetSymbolAddress((void**)&wh, g_wh);
    cudaGetSymbolAddress((void**)&wl, g_wl);
    cudaGetSymbolAddress((void**)&qh, g_qh);
    cudaGetSymbolAddress((void**)&ql, g_ql);
    cudaGetSymbolAddress((void**)&kh, g_kh);
    cudaGetSymbolAddress((void**)&kl, g_kl);
    cudaGetSymbolAddress((void**)&vh, g_vh);
    cudaGetSymbolAddress((void**)&vl, g_vl);
    const size_t WSZ = (size_t)Hh * GK;

    const int gemm_smem = 196608;
    cudaFuncSetAttribute(gemm3<0>, cudaFuncAttributeMaxDynamicSharedMemorySize, gemm_smem);
    cudaFuncSetAttribute(gemm3<1>, cudaFuncAttributeMaxDynamicSharedMemorySize, gemm_smem);
    cudaFuncSetAttribute(flash_mma, cudaFuncAttributeMaxDynamicSharedMemorySize, FLASH_SMEM);

    const dim3 gGemm(Hh / 128, Mm / 256);  // (16, 16)
    const int actN = Mm * Hh;
    const int wN = Hh * Hh;
    const int qkvN = Bb * NHh * Ss * HDd;

    split_pair_kernel<<<(actN + 255) / 256, 256>>>(hs, ah, al, actN);
    split_pair_kernel<<<(wN + 255) / 256, 256>>>(qw, wh, wl, wN);
    split_pair_kernel<<<(wN + 255) / 256, 256>>>(kw, wh + WSZ, wl + WSZ, wN);
    split_pair_kernel<<<(wN + 255) / 256, 256>>>(vw, wh + 2 * WSZ, wl + 2 * WSZ, wN);
    rope_tables_kernel<<<(Ss * 64 + 255) / 256, 256>>>();

    gemm3<1><<<gGemm, 256, gemm_smem>>>(ah, al, wh, wl, qbuf);
    gemm3<1><<<gGemm, 256, gemm_smem>>>(ah, al, wh + WSZ, wl + WSZ, kbuf);
    gemm3<1><<<gGemm, 256, gemm_smem>>>(ah, al, wh + 2 * WSZ, wl + 2 * WSZ, vbuf);

    rope_split_kernel<<<(Bb * NHh * Ss * 64 + 255) / 256, 256>>>(qbuf, kbuf, qh, ql, kh, kl);
    split_pair_kernel<<<(qkvN + 255) / 256, 256>>>(vbuf, vh, vl, qkvN);

    flash_mma<<<dim3(Ss / 128, Bb * NHh), 256, FLASH_SMEM>>>(qh, ql, kh, kl, vh, vl, obuf);

    split_pair_kernel<<<(actN + 255) / 256, 256>>>(obuf, ah, al, actN);
    split_pair_kernel<<<(wN + 255) / 256, 256>>>(ow, wh, wl, wN);
    gemm3<0><<<gGemm, 256, gemm_smem>>>(ah, al, wh, wl, out);
}

// round 7
// speedup vs baseline: 1.0995x; 1.0995x over previous
#include <cuda_runtime.h>
#include <cuda_bf16.h>
#include <cuda_fp16.h>
#include <math.h>
#include <stdint.h>

#define Bb 2
#define Ss 2048
#define Hh 2048
#define NHh 16
#define HDd 128
#define Mm (Bb*Ss)
#define GK 2048
#define GCH 32
#define GNCH (GK/GCH)      // 64

// ---------------- scratch ----------------
__device__ float g_q[(size_t)Bb*NHh*Ss*HDd];
__device__ float g_k[(size_t)Bb*NHh*Ss*HDd];
__device__ float g_cos[Ss*64];
__device__ float g_sin[Ss*64];
__device__ __nv_bfloat16 g_ah[(size_t)Mm*GK];     // activation hi (bf16)
__device__ __nv_bfloat16 g_al[(size_t)Mm*GK];     // activation lo (bf16)
__device__ __nv_bfloat16 g_wh[4][(size_t)Hh*GK];  // weight hi (q,k,v,o)
__device__ __nv_bfloat16 g_wl[4][(size_t)Hh*GK];  // weight lo
// flash fp16 operands
__device__ __half g_qh[(size_t)Bb*NHh*Ss*HDd];
__device__ __half g_ql[(size_t)Bb*NHh*Ss*HDd];
__device__ __half g_kh[(size_t)Bb*NHh*Ss*HDd];
__device__ __half g_vh[(size_t)Bb*NHh*Ss*HDd];

// ---------------- PTX helpers ----------------
__device__ __forceinline__ uint32_t smem_u32(const void* p) {
    uint32_t a;
    asm("{ .reg .u64 t; cvta.to.shared.u64 t, %1; cvt.u32.u64 %0, t; }" : "=r"(a) : "l"(p));
    return a;
}
#define CP_ASYNC16(sa, gp) \
    asm volatile("cp.async.cg.shared.global [%0], [%1], 16;" :: "r"(sa), "l"(gp) : "memory")
#define CP_COMMIT() asm volatile("cp.async.commit_group;" ::: "memory")
#define CP_WAIT0()  asm volatile("cp.async.wait_group 0;" ::: "memory")
#define CP_WAIT1()  asm volatile("cp.async.wait_group 1;" ::: "memory")
#define CP_WAIT2()  asm volatile("cp.async.wait_group 2;" ::: "memory")

__device__ __forceinline__ void ldsm_x4(uint32_t* r, uint32_t addr) {
    asm volatile("ldmatrix.sync.aligned.m8n8.x4.shared.b16 {%0,%1,%2,%3}, [%4];"
        : "=r"(r[0]), "=r"(r[1]), "=r"(r[2]), "=r"(r[3]) : "r"(addr));
}
__device__ __forceinline__ void ldsm_x4_t(uint32_t* r, uint32_t addr) {
    asm volatile("ldmatrix.sync.aligned.m8n8.x4.trans.shared.b16 {%0,%1,%2,%3}, [%4];"
        : "=r"(r[0]), "=r"(r[1]), "=r"(r[2]), "=r"(r[3]) : "r"(addr));
}
__device__ __forceinline__ void mma16816(float* d, const uint32_t* a, const uint32_t* b) {
    asm volatile("mma.sync.aligned.m16n8k16.row.col.f32.bf16.bf16.f32 "
        "{%0,%1,%2,%3}, {%4,%5,%6,%7}, {%8,%9}, {%0,%1,%2,%3};"
        : "+f"(d[0]), "+f"(d[1]), "+f"(d[2]), "+f"(d[3])
        : "r"(a[0]), "r"(a[1]), "r"(a[2]), "r"(a[3]), "r"(b[0]), "r"(b[1]));
}
__device__ __forceinline__ void mma16816h(float* d, const uint32_t* a, const uint32_t* b) {
    asm volatile("mma.sync.aligned.m16n8k16.row.col.f32.f16.f16.f32 "
        "{%0,%1,%2,%3}, {%4,%5,%6,%7}, {%8,%9}, {%0,%1,%2,%3};"
        : "+f"(d[0]), "+f"(d[1]), "+f"(d[2]), "+f"(d[3])
        : "r"(a[0]), "r"(a[1]), "r"(a[2]), "r"(a[3]), "r"(b[0]), "r"(b[1]));
}
#define SWZ32(o) ((o) ^ (((o) >> 3) & 0x30))

// ---------------- hi/lo pair split (bf16) ----------------
__global__ void split_pair_kernel(const float* __restrict__ X,
                                  __nv_bfloat16* __restrict__ Xh,
                                  __nv_bfloat16* __restrict__ Xl, int n)
{
    int idx = blockIdx.x * blockDim.x + threadIdx.x;
    if (idx >= n) return;
    float x = X[idx];
    __nv_bfloat16 hi = __float2bfloat16(x);
    Xh[idx] = hi;
    Xl[idx] = __float2bfloat16(x - __bfloat162float(hi));
}

// ---------------- all-4 weight splits in one launch ----------------
__global__ void split_w4_kernel(const float* __restrict__ w0, const float* __restrict__ w1,
                                const float* __restrict__ w2, const float* __restrict__ w3,
                                __nv_bfloat16* __restrict__ H, __nv_bfloat16* __restrict__ L)
{
    int idx = blockIdx.x * blockDim.x + threadIdx.x;
    const int t = blockIdx.y;
    if (idx >= Hh * Hh) return;
    const float* W = (t == 0) ? w0 : (t == 1) ? w1 : (t == 2) ? w2 : w3;
    float x = W[idx];
    __nv_bfloat16 hi = __float2bfloat16(x);
    const size_t o = (size_t)t * Hh * GK + idx;
    H[o] = hi;
    L[o] = __float2bfloat16(x - __bfloat162float(hi));
}

// ---------------- HMMA GEMM: CTA 256x128, 8 warps 64x64, 4-stage, hi/lo reuse --
// C = Ah*Bh^T + Al*Bh^T + Ah*Bl^T
// MODE 0: fp32 row-major [M,N]; MODE 1: fp32 head scatter; MODE 2: fp16 head scatter
#define STG 49152u
#define AhO 0u
#define AlO 16384u
#define BhO 32768u
#define BlO 40960u

template <int MODE>
__global__ __launch_bounds__(256, 1) void gemm3(const __nv_bfloat16* __restrict__ Ah,
                                                const __nv_bfloat16* __restrict__ Al,
                                                const __nv_bfloat16* __restrict__ Bh,
                                                const __nv_bfloat16* __restrict__ Bl,
                                                void* __restrict__ Cv)
{
    extern __shared__ char smem[];
    const uint32_t sb = smem_u32(smem);
    const int tid = threadIdx.x;
    const int wid = tid >> 5;
    const int lane = tid & 31;
    const int n0 = blockIdx.x * 128;
    const int m0 = blockIdx.y * 256;
    const int wm = wid & 3;
    const int wn = wid >> 2;

    float acc[4][8][4];
#pragma unroll
    for (int mi = 0; mi < 4; mi++)
#pragma unroll
        for (int ni = 0; ni < 8; ni++)
#pragma unroll
            for (int q = 0; q < 4; q++) acc[mi][ni][q] = 0.f;

#define LOAD_STAGE(ci, st) do {                                                     \
    const int _k0 = (ci) * GCH;                                                     \
    const uint32_t _bs = sb + (uint32_t)(st) * STG;                                 \
    _Pragma("unroll")                                                               \
    for (int _i = 0; _i < 4; _i++) {                                                \
        int _idx = tid + 256 * _i;                                                  \
        int _r = _idx >> 2;                                                         \
        int _cb = (_idx & 3) * 16;                                                  \
        CP_ASYNC16(_bs + AhO + SWZ32(_r * 64 + _cb),                                \
                   Ah + (size_t)(m0 + _r) * GK + _k0 + (_cb >> 1));                 \
    }                                                                               \
    _Pragma("unroll")                                                               \
    for (int _i = 0; _i < 4; _i++) {                                                \
        int _idx = tid + 256 * _i;                                                  \
        int _r = _idx >> 2;                                                         \
        int _cb = (_idx & 3) * 16;                                                  \
        CP_ASYNC16(_bs + AlO + SWZ32(_r * 64 + _cb),                                \
                   Al + (size_t)(m0 + _r) * GK + _k0 + (_cb >> 1));                 \
    }                                                                               \
    _Pragma("unroll")                                                               \
    for (int _i = 0; _i < 2; _i++) {                                                \
        int _idx = tid + 256 * _i;                                                  \
        int _r = _idx >> 2;                                                         \
        int _cb = (_idx & 3) * 16;                                                  \
        CP_ASYNC16(_bs + BhO + SWZ32(_r * 64 + _cb),                                \
                   Bh + (size_t)(n0 + _r) * GK + _k0 + (_cb >> 1));                 \
    }                                                                               \
    _Pragma("unroll")                                                               \
    for (int _i = 0; _i < 2; _i++) {                                                \
        int _idx = tid + 256 * _i;                                                  \
        int _r = _idx >> 2;                                                         \
        int _cb = (_idx & 3) * 16;                                                  \
        CP_ASYNC16(_bs + BlO + SWZ32(_r * 64 + _cb),                                \
                   Bl + (size_t)(n0 + _r) * GK + _k0 + (_cb >> 1));                 \
    }                                                                               \
    CP_COMMIT();                                                                    \
} while (0)

    const uint32_t a_half = (uint32_t)((lane >> 4) * 16);
    const uint32_t a_xor = (uint32_t)((((lane & 15) >> 1) & 3) * 16);
    uint32_t aRow[4];
#pragma unroll
    for (int mi = 0; mi < 4; mi++)
        aRow[mi] = (uint32_t)((wm * 64 + mi * 16 + (lane & 15)) * 64);

    const int b_lrow = (lane & 7) + ((lane >> 4) << 3);
    const uint32_t b_half = (uint32_t)(((lane >> 3) & 1) * 16);
    const uint32_t b_xor = (uint32_t)((((lane & 7) >> 1) & 3) * 16);
    uint32_t bRow[4];
#pragma unroll
    for (int nt = 0; nt < 4; nt++)
        bRow[nt] = (uint32_t)((wn * 64 + nt * 16 + b_lrow) * 64);

    LOAD_STAGE(0, 0);
    LOAD_STAGE(1, 1);
    LOAD_STAGE(2, 2);

    for (int c = 0; c < GNCH; c++) {
        if (c <= GNCH - 3) CP_WAIT2();
        else if (c == GNCH - 2) CP_WAIT1();
        else CP_WAIT0();
        __syncthreads();
        if (c + 3 < GNCH) LOAD_STAGE(c + 3, (c + 3) & 3);

        const uint32_t bs = sb + (uint32_t)(c & 3) * STG;
#pragma unroll
        for (int kk = 0; kk < 2; kk++) {
            const uint32_t acol = ((uint32_t)(kk * 32) + a_half) ^ a_xor;
            const uint32_t bcol = ((uint32_t)(kk * 32) + b_half) ^ b_xor;
            uint32_t ah4[4][4], bh4[4][4], xx4[4][4];
#pragma unroll
            for (int mi = 0; mi < 4; mi++)
                ldsm_x4(ah4[mi], bs + AhO + aRow[mi] + acol);
#pragma unroll
            for (int nt = 0; nt < 4; nt++)
                ldsm_x4(bh4[nt], bs + BhO + bRow[nt] + bcol);
#pragma unroll
            for (int mi = 0; mi < 4; mi++)
#pragma unroll
                for (int nt = 0; nt < 4; nt++) {
                    mma16816(acc[mi][2 * nt],     ah4[mi], bh4[nt]);
                    mma16816(acc[mi][2 * nt + 1], ah4[mi], bh4[nt] + 2);
                }
#pragma unroll
            for (int mi = 0; mi < 4; mi++)
                ldsm_x4(xx4[mi], bs + AlO + aRow[mi] + acol);
#pragma unroll
            for (int mi = 0; mi < 4; mi++)
#pragma unroll
                for (int nt = 0; nt < 4; nt++) {
                    mma16816(acc[mi][2 * nt],     xx4[mi], bh4[nt]);
                    mma16816(acc[mi][2 * nt + 1], xx4[mi], bh4[nt] + 2);
                }
#pragma unroll
            for (int nt = 0; nt < 4; nt++)
                ldsm_x4(xx4[nt], bs + BlO + bRow[nt] + bcol);
#pragma unroll
            for (int mi = 0; mi < 4; mi++)
#pragma unroll
                for (int nt = 0; nt < 4; nt++) {
                    mma16816(acc[mi][2 * nt],     ah4[mi], xx4[nt]);
                    mma16816(acc[mi][2 * nt + 1], ah4[mi], xx4[nt] + 2);
                }
        }
    }

    const int er = lane >> 2;
    const int ec = (lane & 3) * 2;
#pragma unroll
    for (int mi = 0; mi < 4; mi++) {
#pragma unroll
        for (int ni = 0; ni < 8; ni++) {
            const int m = m0 + wm * 64 + mi * 16 + er;
            const int n = n0 + wn * 64 + ni * 8 + ec;
            if (MODE == 0) {
                float* C = (float*)Cv;
                *(float2*)(C + (size_t)m * Hh + n) =
                    make_float2(acc[mi][ni][0], acc[mi][ni][1]);
                *(float2*)(C + (size_t)(m + 8) * Hh + n) =
                    make_float2(acc[mi][ni][2], acc[mi][ni][3]);
            } else {
                const int b_ = m >> 11;
                const int s_ = m & (Ss - 1);
                const int h_ = n >> 7;
                const int d_ = n & (HDd - 1);
                const size_t o0 = (((size_t)b_ * NHh + h_) * Ss + s_) * HDd + d_;
                if (MODE == 1) {
                    float* C = (float*)Cv;
                    *(float2*)(C + o0) = make_float2(acc[mi][ni][0], acc[mi][ni][1]);
                    *(float2*)(C + o0 + 8 * HDd) = make_float2(acc[mi][ni][2], acc[mi][ni][3]);
                } else {
                    __half* C = (__half*)Cv;
                    *(__half2*)(C + o0) = __floats2half2_rn(acc[mi][ni][0], acc[mi][ni][1]);
                    *(__half2*)(C + o0 + 8 * HDd) = __floats2half2_rn(acc[mi][ni][2], acc[mi][ni][3]);
                }
            }
        }
    }
#undef LOAD_STAGE
}

// ---------------- RoPE tables ----------------
__global__ void rope_tables_kernel()
{
    int idx = blockIdx.x * blockDim.x + threadIdx.x;
    if (idx >= Ss * 64) return;
    int s = idx >> 6;
    int d = idx & 63;
    float invf = (float)pow(10000.0, -(double)d * (1.0 / 64.0));
    float ang = (float)s * invf;
    float c, sn;
    sincosf(ang, &sn, &c);
    g_cos[idx] = c;
    g_sin[idx] = sn;
}

// ---------------- RoPE apply + fp16 split (Q pair scaled; K single plane) ------
__global__ void rope_split_kernel(const float* __restrict__ q, const float* __restrict__ k,
                                  __half* __restrict__ qh, __half* __restrict__ ql,
                                  __half* __restrict__ kh)
{
    int idx = blockIdx.x * blockDim.x + threadIdx.x;
    if (idx >= Bb * NHh * Ss * 64) return;
    const int d = idx & 63;
    const int s = (idx >> 6) & (Ss - 1);
    const int bh = idx >> 17;
    const int t = (s << 6) + d;
    const float c = g_cos[t];
    const float sn = g_sin[t];
    const float rscale = 0.08838834764831845f;
    const size_t base = ((size_t)bh * Ss + s) * HDd + d;

    float q1 = q[base], q2 = q[base + 64];
    float r1 = (q1 * c - q2 * sn) * rscale;
    float r2 = (q2 * c + q1 * sn) * rscale;
    __half h1 = __float2half_rn(r1);
    __half h2 = __float2half_rn(r2);
    qh[base] = h1; qh[base + 64] = h2;
    ql[base] = __float2half_rn(r1 - __half2float(h1));
    ql[base + 64] = __float2half_rn(r2 - __half2float(h2));

    float k1 = k[base], k2 = k[base + 64];
    kh[base]      = __float2half_rn(k1 * c - k2 * sn);
    kh[base + 64] = __float2half_rn(k2 * c + k1 * sn);
}

// ---------------- fp16 HMMA causal flash attention, BM=128, BN=64 ---------------
// S = (Qh+Ql)*fp16(K);  O = (Ph+Pl)*fp16(V).  Output: bf16 hi/lo activation [M,H].
#define QsO 0u
#define KsO 65536u
#define VsO 98304u
#define FLASH_SMEM 131072

__global__ __launch_bounds__(256, 1) void flash_mma(
    const __half* __restrict__ qh, const __half* __restrict__ ql,
    const __half* __restrict__ kh, const __half* __restrict__ vh,
    __nv_bfloat16* __restrict__ Oh, __nv_bfloat16* __restrict__ Ol)
{
    extern __shared__ char smem[];
    const uint32_t sb = smem_u32(smem);
    const int tid = threadIdx.x;
    const int lane = tid & 31;
    const int w = tid >> 5;
    const int qb = (gridDim.x - 1) - blockIdx.x;
    const int bh = blockIdx.y;
    const int b = bh >> 4, h = bh & 15;
    const int qlo = qb * 128;
    const int wr = w * 16;

    // Q tile: 128 rows x 512B (hi|lo planes)
#pragma unroll
    for (int i = 0; i < 16; i++) {
        int idx = tid + 256 * i;
        int row = idx >> 5;
        int off = (idx & 31) * 16;
        const __half* src = (off < 256)
            ? qh + ((size_t)bh * Ss + qlo + row) * HDd + (off >> 1)
            : ql + ((size_t)bh * Ss + qlo + row) * HDd + ((off - 256) >> 1);
        uint32_t dst = sb + QsO + row * 512 + (off & ~127) + ((off & 127) ^ ((row & 7) << 4));
        CP_ASYNC16(dst, src);
    }
    CP_COMMIT();

#define LOAD_KV(kb_, s_) do {                                                        \
    const int _klo = (kb_) * 64;                                                     \
    _Pragma("unroll")                                                                \
    for (int _i = 0; _i < 4; _i++) {                                                 \
        int _idx = tid + 256 * _i;                                                   \
        int _row = _idx >> 4;                                                        \
        int _off = (_idx & 15) * 16;                                                 \
        const __half* _src = kh + ((size_t)bh * Ss + _klo + _row) * HDd + (_off >> 1); \
        uint32_t _dst = sb + KsO + (s_) * 16384u + _row * 256 + (_off & ~127)        \
                        + ((_off & 127) ^ ((_row & 7) << 4));                        \
        CP_ASYNC16(_dst, _src);                                                      \
    }                                                                                \
    _Pragma("unroll")                                                                \
    for (int _i = 0; _i < 4; _i++) {                                                 \
        int _idx = tid + 256 * _i;                                                   \
        int _row = _idx >> 4;                                                        \
        int _off = (_idx & 15) * 16;                                                 \
        const __half* _src = vh + ((size_t)bh * Ss + _klo + _row) * HDd + (_off >> 1); \
        uint32_t _dst = sb + VsO + (s_) * 16384u + _row * 256 + (_off & ~127)        \
                        + ((_off & 127) ^ ((_row & 7) << 4));                        \
        CP_ASYNC16(_dst, _src);                                                      \
    }                                                                                \
    CP_COMMIT();                                                                     \
} while (0)

    LOAD_KV(0, 0);

    const int a_row = wr + (lane & 15);
    const uint32_t a_base = sb + QsO + a_row * 512;
    const uint32_t a_half = (uint32_t)((lane >> 4) * 16);
    const uint32_t a_xor = (uint32_t)((a_row & 7) * 16);

    const int b_rowk = (lane & 7) + ((lane >> 4) << 3);
    const uint32_t b_halfk = (uint32_t)(((lane >> 3) & 1) * 16);
    const uint32_t b_xork = (uint32_t)((lane & 7) * 16);

    const int v_row = (lane & 7) + (((lane >> 3) & 1) << 3);
    const uint32_t v_half = (uint32_t)((lane >> 4) * 16);
    const uint32_t v_xor = (uint32_t)((lane & 7) * 16);

    float oacc[16][4];
#pragma unroll
    for (int i = 0; i < 16; i++)
#pragma unroll
        for (int q = 0; q < 4; q++) oacc[i][q] = 0.f;
    float m0 = -1e30f, m1 = -1e30f, l0 = 0.f, l1 = 0.f;

    const int row_q0 = qlo + wr + (lane >> 2);
    const int nkb = 2 * qb + 2;

    for (int kb = 0; kb < nkb; kb++) {
        const int klo = kb * 64;
        CP_WAIT0();
        __syncthreads();
        if (kb + 1 < nkb) LOAD_KV(kb + 1, (kb + 1) & 1);

        const bool warp_skip = (klo > qlo + wr + 15);
        if (!warp_skip) {
            const uint32_t kbase = sb + KsO + (uint32_t)(kb & 1) * 16384u;
            const uint32_t vbase = sb + VsO + (uint32_t)(kb & 1) * 16384u;

            float sacc[8][4];
#pragma unroll
            for (int i = 0; i < 8; i++)
#pragma unroll
                for (int q = 0; q < 4; q++) sacc[i][q] = 0.f;

            // S = Qh*K + Ql*K   (fp16, K single plane)
#pragma unroll
            for (int kk = 0; kk < 8; kk++) {
                const uint32_t acol = ((uint32_t)((kk & 3) * 32) + a_half) ^ a_xor;
                const uint32_t achunk = (uint32_t)((kk >> 2) * 128);
                uint32_t ahi[4], alo[4];
                ldsm_x4(ahi, a_base + achunk + acol);
                ldsm_x4(alo, a_base + 256u + achunk + acol);
                const uint32_t bcol = ((uint32_t)((kk & 3) * 32) + b_halfk) ^ b_xork;
#pragma unroll
                for (int g = 0; g < 4; g++) {
                    uint32_t bk[4];
                    ldsm_x4(bk, kbase + (uint32_t)((g * 16 + b_rowk) * 256) + achunk + bcol);
                    mma16816h(sacc[2 * g],     ahi, bk);
                    mma16816h(sacc[2 * g + 1], ahi, bk + 2);
                    mma16816h(sacc[2 * g],     alo, bk);
                    mma16816h(sacc[2 * g + 1], alo, bk + 2);
                }
            }

            if (klo + 63 > qlo + wr) {
#pragma unroll
                for (int nt = 0; nt < 8; nt++) {
                    const int cb = klo + nt * 8 + (lane & 3) * 2;
                    if (cb     > row_q0)     sacc[nt][0] = -1e30f;
                    if (cb + 1 > row_q0)     sacc[nt][1] = -1e30f;
                    if (cb     > row_q0 + 8) sacc[nt][2] = -1e30f;
                    if (cb + 1 > row_q0 + 8) sacc[nt][3] = -1e30f;
                }
            }

            float nm0 = -1e30f, nm1 = -1e30f;
#pragma unroll
            for (int nt = 0; nt < 8; nt++) {
                nm0 = fmaxf(nm0, fmaxf(sacc[nt][0], sacc[nt][1]));
                nm1 = fmaxf(nm1, fmaxf(sacc[nt][2], sacc[nt][3]));
            }
            nm0 = fmaxf(nm0, __shfl_xor_sync(0xffffffffu, nm0, 1));
            nm0 = fmaxf(nm0, __shfl_xor_sync(0xffffffffu, nm0, 2));
            nm1 = fmaxf(nm1, __shfl_xor_sync(0xffffffffu, nm1, 1));
            nm1 = fmaxf(nm1, __shfl_xor_sync(0xffffffffu, nm1, 2));
            nm0 = fmaxf(m0, nm0);
            nm1 = fmaxf(m1, nm1);
            const float alpha0 = __expf(m0 - nm0);
            const float alpha1 = __expf(m1 - nm1);
            m0 = nm0; m1 = nm1;

            uint32_t phi[8][2], plo[8][2];
            float s0 = 0.f, s1 = 0.f;
#pragma unroll
            for (int nt = 0; nt < 8; nt++) {
                float p00 = __expf(sacc[nt][0] - m0);
                float p01 = __expf(sacc[nt][1] - m0);
                float p10 = __expf(sacc[nt][2] - m1);
                float p11 = __expf(sacc[nt][3] - m1);
                s0 += p00 + p01;
                s1 += p10 + p11;
                __half2 h0 = __floats2half2_rn(p00, p01);
                __half2 h1 = __floats2half2_rn(p10, p11);
                phi[nt][0] = *(uint32_t*)&h0;
                phi[nt][1] = *(uint32_t*)&h1;
                float2 f0 = __half22float2(h0);
                float2 f1 = __half22float2(h1);
                __half2 e0 = __floats2half2_rn(p00 - f0.x, p01 - f0.y);
                __half2 e1 = __floats2half2_rn(p10 - f1.x, p11 - f1.y);
                plo[nt][0] = *(uint32_t*)&e0;
                plo[nt][1] = *(uint32_t*)&e1;
            }
            s0 += __shfl_xor_sync(0xffffffffu, s0, 1);
            s0 += __shfl_xor_sync(0xffffffffu, s0, 2);
            s1 += __shfl_xor_sync(0xffffffffu, s1, 1);
            s1 += __shfl_xor_sync(0xffffffffu, s1, 2);
            l0 = l0 * alpha0 + s0;
            l1 = l1 * alpha1 + s1;
#pragma unroll
            for (int dt = 0; dt < 16; dt++) {
                oacc[dt][0] *= alpha0; oacc[dt][1] *= alpha0;
                oacc[dt][2] *= alpha1; oacc[dt][3] *= alpha1;
            }

            // O += Ph*V + Pl*V  (fp16, V single plane)
#pragma unroll
            for (int jt = 0; jt < 4; jt++) {
                uint32_t ah[4] = { phi[2 * jt][0], phi[2 * jt][1],
                                   phi[2 * jt + 1][0], phi[2 * jt + 1][1] };
                uint32_t al[4] = { plo[2 * jt][0], plo[2 * jt][1],
                                   plo[2 * jt + 1][0], plo[2 * jt + 1][1] };
                const uint32_t vrow = (uint32_t)((jt * 16 + v_row) * 256);
#pragma unroll
                for (int g = 0; g < 8; g++) {
                    const uint32_t colb = (uint32_t)(g * 32) + v_half;
                    const uint32_t voff = vrow + (colb & ~127u) + ((colb & 127u) ^ v_xor);
                    uint32_t bv[4];
                    ldsm_x4_t(bv, vbase + voff);
                    mma16816h(oacc[2 * g],     ah, bv);
                    mma16816h(oacc[2 * g + 1], ah, bv + 2);
                    mma16816h(oacc[2 * g],     al, bv);
                    mma16816h(oacc[2 * g + 1], al, bv + 2);
                }
            }
        }
        __syncthreads();
    }

    // epilogue: normalize + bf16 hi/lo split straight into activation buffers
    const float inv0 = 1.f / l0;
    const float inv1 = 1.f / l1;
    const int col0 = h * HDd + (lane & 3) * 2;
    const size_t base0 = ((size_t)b * Ss + row_q0) * Hh + col0;
    const size_t base1 = ((size_t)b * Ss + row_q0 + 8) * Hh + col0;
#pragma unroll
    for (int dt = 0; dt < 16; dt++) {
        float v00 = oacc[dt][0] * inv0, v01 = oacc[dt][1] * inv0;
        float v10 = oacc[dt][2] * inv1, v11 = oacc[dt][3] * inv1;
        __nv_bfloat162 h0 = __floats2bfloat162_rn(v00, v01);
        __nv_bfloat162 h1 = __floats2bfloat162_rn(v10, v11);
        float2 f0 = __bfloat1622float2(h0);
        float2 f1 = __bfloat1622float2(h1);
        __nv_bfloat162 e0 = __floats2bfloat162_rn(v00 - f0.x, v01 - f0.y);
        __nv_bfloat162 e1 = __floats2bfloat162_rn(v10 - f1.x, v11 - f1.y);
        *(__nv_bfloat162*)(Oh + base0 + dt * 8) = h0;
        *(__nv_bfloat162*)(Ol + base0 + dt * 8) = e0;
        *(__nv_bfloat162*)(Oh + base1 + dt * 8) = h1;
        *(__nv_bfloat162*)(Ol + base1 + dt * 8) = e1;
    }
#undef LOAD_KV
}

// ---------------- launch ----------------
extern "C" void kernel_launch(void* const* d_in, const int* in_sizes, int n_in,
                              void* d_out, int out_size)
{
    (void)in_sizes; (void)n_in; (void)out_size;
    const float* hs = (const float*)d_in[0];
    const float* qw = (const float*)d_in[1];
    const float* kw = (const float*)d_in[2];
    const float* vw = (const float*)d_in[3];
    const float* ow = (const float*)d_in[4];
    float* out = (float*)d_out;

    float *qbuf, *kbuf;
    __nv_bfloat16 *ah, *al, *wh, *wl;
    __half *qh, *ql, *kh, *vh;
    cudaGetSymbolAddress((void**)&qbuf, g_q);
    cudaGetSymbolAddress((void**)&kbuf, g_k);
    cudaGetSymbolAddress((void**)&ah, g_ah);
    cudaGetSymbolAddress((void**)&al, g_al);
    cudaGetSymbolAddress((void**)&wh, g_wh);
    cudaGetSymbolAddress((void**)&wl, g_wl);
    cudaGetSymbolAddress((void**)&qh, g_qh);
    cudaGetSymbolAddress((void**)&ql, g_ql);
    cudaGetSymbolAddress((void**)&kh, g_kh);
    cudaGetSymbolAddress((void**)&vh, g_vh);
    const size_t WSZ = (size_t)Hh * GK;

    const int gemm_smem = 196608;
    cudaFuncSetAttribute(gemm3<0>, cudaFuncAttributeMaxDynamicSharedMemorySize, gemm_smem);
    cudaFuncSetAttribute(gemm3<1>, cudaFuncAttributeMaxDynamicSharedMemorySize, gemm_smem);
    cudaFuncSetAttribute(gemm3<2>, cudaFuncAttributeMaxDynamicSharedMemorySize, gemm_smem);
    cudaFuncSetAttribute(flash_mma, cudaFuncAttributeMaxDynamicSharedMemorySize, FLASH_SMEM);

    const dim3 gGemm(Hh / 128, Mm / 256);  // (16, 16)
    const int actN = Mm * Hh;
    const int wN = Hh * Hh;

    split_pair_kernel<<<(actN + 255) / 256, 256>>>(hs, ah, al, actN);
    split_w4_kernel<<<dim3((wN + 255) / 256, 4), 256>>>(qw, kw, vw, ow, wh, wl);
    rope_tables_kernel<<<(Ss * 64 + 255) / 256, 256>>>();

    gemm3<1><<<gGemm, 256, gemm_smem>>>(ah, al, wh, wl, qbuf);
    gemm3<1><<<gGemm, 256, gemm_smem>>>(ah, al, wh + WSZ, wl + WSZ, kbuf);
    gemm3<2><<<gGemm, 256, gemm_smem>>>(ah, al, wh + 2 * WSZ, wl + 2 * WSZ, vh);

    rope_split_kernel<<<(Bb * NHh * Ss * 64 + 255) / 256, 256>>>(qbuf, kbuf, qh, ql, kh);

    // flash overwrites ah/al with the attention-output activation (bf16 hi/lo)
    flash_mma<<<dim3(Ss / 128, Bb * NHh), 256, FLASH_SMEM>>>(qh, ql, kh, vh, ah, al);

    gemm3<0><<<gGemm, 256, gemm_smem>>>(ah, al, wh + 3 * WSZ, wl + 3 * WSZ, out);
}

// round 8
// speedup vs baseline: 1.4896x; 1.3548x over previous
#include <cuda_runtime.h>
#include <cuda_bf16.h>
#include <cuda_fp16.h>
#include <math.h>
#include <stdint.h>

#define Bb 2
#define Ss 2048
#define Hh 2048
#define NHh 16
#define HDd 128
#define Mm (Bb*Ss)
#define GK 2048
#define GCH 32
#define GNCH (GK/GCH)      // 64

// ---------------- scratch ----------------
__device__ float g_q[(size_t)Bb*NHh*Ss*HDd];
__device__ float g_k[(size_t)Bb*NHh*Ss*HDd];
__device__ float g_cos[Ss*64];
__device__ float g_sin[Ss*64];
__device__ __half g_ah[(size_t)Mm*GK];         // activation hi (fp16)
__device__ __half g_al[(size_t)Mm*GK];         // activation lo (fp16)
__device__ __half g_w[4][(size_t)Hh*GK];       // weights fp16 (q,k,v,o)
// flash fp16 operands
__device__ __half g_qh[(size_t)Bb*NHh*Ss*HDd];
__device__ __half g_ql[(size_t)Bb*NHh*Ss*HDd];
__device__ __half g_kh[(size_t)Bb*NHh*Ss*HDd];
__device__ __half g_vh[(size_t)Bb*NHh*Ss*HDd];

// ---------------- PTX helpers ----------------
__device__ __forceinline__ uint32_t smem_u32(const void* p) {
    uint32_t a;
    asm("{ .reg .u64 t; cvta.to.shared.u64 t, %1; cvt.u32.u64 %0, t; }" : "=r"(a) : "l"(p));
    return a;
}
#define CP_ASYNC16(sa, gp) \
    asm volatile("cp.async.cg.shared.global [%0], [%1], 16;" :: "r"(sa), "l"(gp) : "memory")
#define CP_COMMIT() asm volatile("cp.async.commit_group;" ::: "memory")
#define CP_WAIT0()  asm volatile("cp.async.wait_group 0;" ::: "memory")
#define CP_WAIT1()  asm volatile("cp.async.wait_group 1;" ::: "memory")
#define CP_WAIT2()  asm volatile("cp.async.wait_group 2;" ::: "memory")

__device__ __forceinline__ void ldsm_x4(uint32_t* r, uint32_t addr) {
    asm volatile("ldmatrix.sync.aligned.m8n8.x4.shared.b16 {%0,%1,%2,%3}, [%4];"
        : "=r"(r[0]), "=r"(r[1]), "=r"(r[2]), "=r"(r[3]) : "r"(addr));
}
__device__ __forceinline__ void ldsm_x4_t(uint32_t* r, uint32_t addr) {
    asm volatile("ldmatrix.sync.aligned.m8n8.x4.trans.shared.b16 {%0,%1,%2,%3}, [%4];"
        : "=r"(r[0]), "=r"(r[1]), "=r"(r[2]), "=r"(r[3]) : "r"(addr));
}
__device__ __forceinline__ void mma16816h(float* d, const uint32_t* a, const uint32_t* b) {
    asm volatile("mma.sync.aligned.m16n8k16.row.col.f32.f16.f16.f32 "
        "{%0,%1,%2,%3}, {%4,%5,%6,%7}, {%8,%9}, {%0,%1,%2,%3};"
        : "+f"(d[0]), "+f"(d[1]), "+f"(d[2]), "+f"(d[3])
        : "r"(a[0]), "r"(a[1]), "r"(a[2]), "r"(a[3]), "r"(b[0]), "r"(b[1]));
}
#define SWZ32(o) ((o) ^ (((o) >> 3) & 0x30))

// ---------------- fp16 hi/lo pair split (activations) ----------------
__global__ void split_pair_half(const float* __restrict__ X,
                                __half* __restrict__ Xh,
                                __half* __restrict__ Xl, int n)
{
    int idx = blockIdx.x * blockDim.x + threadIdx.x;
    if (idx >= n) return;
    float x = X[idx];
    __half hi = __float2half_rn(x);
    Xh[idx] = hi;
    Xl[idx] = __float2half_rn(x - __half2float(hi));
}

// ---------------- all-4 weight fp16 converts in one launch ----------------
__global__ void convert_w4(const float* __restrict__ w0, const float* __restrict__ w1,
                           const float* __restrict__ w2, const float* __restrict__ w3,
                           __half* __restrict__ H)
{
    int idx = blockIdx.x * blockDim.x + threadIdx.x;
    const int t = blockIdx.y;
    if (idx >= Hh * Hh) return;
    const float* W = (t == 0) ? w0 : (t == 1) ? w1 : (t == 2) ? w2 : w3;
    H[(size_t)t * Hh * GK + idx] = __float2half_rn(W[idx]);
}

// ---------------- fp16 2-product GEMM: CTA 128x128, 4 warps 64x64, 4-stage -----
// C = Ah*B^T + Al*B^T  (fp32 accum)
// MODE 0: fp32 row-major; MODE 1: fp32 head scatter; MODE 2: fp16 head scatter
#define STG2 24576u
#define AhO2 0u
#define AlO2 8192u
#define BO2  16384u

template <int MODE>
__global__ __launch_bounds__(128, 2) void gemm2p(const __half* __restrict__ Ah,
                                                 const __half* __restrict__ Al,
                                                 const __half* __restrict__ Bw,
                                                 void* __restrict__ Cv)
{
    extern __shared__ char smem[];
    const uint32_t sb = smem_u32(smem);
    const int tid = threadIdx.x;
    const int wid = tid >> 5;
    const int lane = tid & 31;
    const int n0 = blockIdx.x * 128;
    const int m0 = blockIdx.y * 128;
    const int wm = wid & 1;
    const int wn = wid >> 1;

    float acc[4][8][4];
#pragma unroll
    for (int mi = 0; mi < 4; mi++)
#pragma unroll
        for (int ni = 0; ni < 8; ni++)
#pragma unroll
            for (int q = 0; q < 4; q++) acc[mi][ni][q] = 0.f;

#define LOAD_STAGE(ci, st) do {                                                     \
    const int _k0 = (ci) * GCH;                                                     \
    const uint32_t _bs = sb + (uint32_t)(st) * STG2;                                \
    _Pragma("unroll")                                                               \
    for (int _i = 0; _i < 4; _i++) {                                                \
        int _idx = tid + 128 * _i;                                                  \
        int _r = _idx >> 2;                                                         \
        int _cb = (_idx & 3) * 16;                                                  \
        CP_ASYNC16(_bs + AhO2 + SWZ32(_r * 64 + _cb),                               \
                   Ah + (size_t)(m0 + _r) * GK + _k0 + (_cb >> 1));                 \
    }                                                                               \
    _Pragma("unroll")                                                               \
    for (int _i = 0; _i < 4; _i++) {                                                \
        int _idx = tid + 128 * _i;                                                  \
        int _r = _idx >> 2;                                                         \
        int _cb = (_idx & 3) * 16;                                                  \
        CP_ASYNC16(_bs + AlO2 + SWZ32(_r * 64 + _cb),                               \
                   Al + (size_t)(m0 + _r) * GK + _k0 + (_cb >> 1));                 \
    }                                                                               \
    _Pragma("unroll")                                                               \
    for (int _i = 0; _i < 4; _i++) {                                                \
        int _idx = tid + 128 * _i;                                                  \
        int _r = _idx >> 2;                                                         \
        int _cb = (_idx & 3) * 16;                                                  \
        CP_ASYNC16(_bs + BO2 + SWZ32(_r * 64 + _cb),                                \
                   Bw + (size_t)(n0 + _r) * GK + _k0 + (_cb >> 1));                 \
    }                                                                               \
    CP_COMMIT();                                                                    \
} while (0)

    const uint32_t a_half = (uint32_t)((lane >> 4) * 16);
    const uint32_t a_xor = (uint32_t)((((lane & 15) >> 1) & 3) * 16);
    uint32_t aRow[4];
#pragma unroll
    for (int mi = 0; mi < 4; mi++)
        aRow[mi] = (uint32_t)((wm * 64 + mi * 16 + (lane & 15)) * 64);

    const int b_lrow = (lane & 7) + ((lane >> 4) << 3);
    const uint32_t b_half = (uint32_t)(((lane >> 3) & 1) * 16);
    const uint32_t b_xor = (uint32_t)((((lane & 7) >> 1) & 3) * 16);
    uint32_t bRow[4];
#pragma unroll
    for (int nt = 0; nt < 4; nt++)
        bRow[nt] = (uint32_t)((wn * 64 + nt * 16 + b_lrow) * 64);

    LOAD_STAGE(0, 0);
    LOAD_STAGE(1, 1);
    LOAD_STAGE(2, 2);

    for (int c = 0; c < GNCH; c++) {
        if (c <= GNCH - 3) CP_WAIT2();
        else if (c == GNCH - 2) CP_WAIT1();
        else CP_WAIT0();
        __syncthreads();
        if (c + 3 < GNCH) LOAD_STAGE(c + 3, (c + 3) & 3);

        const uint32_t bs = sb + (uint32_t)(c & 3) * STG2;
#pragma unroll
        for (int kk = 0; kk < 2; kk++) {
            const uint32_t acol = ((uint32_t)(kk * 32) + a_half) ^ a_xor;
            const uint32_t bcol = ((uint32_t)(kk * 32) + b_half) ^ b_xor;
            uint32_t ah4[4][4], b4[4][4], al4[4][4];
#pragma unroll
            for (int mi = 0; mi < 4; mi++)
                ldsm_x4(ah4[mi], bs + AhO2 + aRow[mi] + acol);
#pragma unroll
            for (int nt = 0; nt < 4; nt++)
                ldsm_x4(b4[nt], bs + BO2 + bRow[nt] + bcol);
#pragma unroll
            for (int mi = 0; mi < 4; mi++)
#pragma unroll
                for (int nt = 0; nt < 4; nt++) {
                    mma16816h(acc[mi][2 * nt],     ah4[mi], b4[nt]);
                    mma16816h(acc[mi][2 * nt + 1], ah4[mi], b4[nt] + 2);
                }
#pragma unroll
            for (int mi = 0; mi < 4; mi++)
                ldsm_x4(al4[mi], bs + AlO2 + aRow[mi] + acol);
#pragma unroll
            for (int mi = 0; mi < 4; mi++)
#pragma unroll
                for (int nt = 0; nt < 4; nt++) {
                    mma16816h(acc[mi][2 * nt],     al4[mi], b4[nt]);
                    mma16816h(acc[mi][2 * nt + 1], al4[mi], b4[nt] + 2);
                }
        }
    }

    const int er = lane >> 2;
    const int ec = (lane & 3) * 2;
#pragma unroll
    for (int mi = 0; mi < 4; mi++) {
#pragma unroll
        for (int ni = 0; ni < 8; ni++) {
            const int m = m0 + wm * 64 + mi * 16 + er;
            const int n = n0 + wn * 64 + ni * 8 + ec;
            if (MODE == 0) {
                float* C = (float*)Cv;
                *(float2*)(C + (size_t)m * Hh + n) =
                    make_float2(acc[mi][ni][0], acc[mi][ni][1]);
                *(float2*)(C + (size_t)(m + 8) * Hh + n) =
                    make_float2(acc[mi][ni][2], acc[mi][ni][3]);
            } else {
                const int b_ = m >> 11;
                const int s_ = m & (Ss - 1);
                const int h_ = n >> 7;
                const int d_ = n & (HDd - 1);
                const size_t o0 = (((size_t)b_ * NHh + h_) * Ss + s_) * HDd + d_;
                if (MODE == 1) {
                    float* C = (float*)Cv;
                    *(float2*)(C + o0) = make_float2(acc[mi][ni][0], acc[mi][ni][1]);
                    *(float2*)(C + o0 + 8 * HDd) = make_float2(acc[mi][ni][2], acc[mi][ni][3]);
                } else {
                    __half* C = (__half*)Cv;
                    *(__half2*)(C + o0) = __floats2half2_rn(acc[mi][ni][0], acc[mi][ni][1]);
                    *(__half2*)(C + o0 + 8 * HDd) = __floats2half2_rn(acc[mi][ni][2], acc[mi][ni][3]);
                }
            }
        }
    }
#undef LOAD_STAGE
}

// ---------------- RoPE tables ----------------
__global__ void rope_tables_kernel()
{
    int idx = blockIdx.x * blockDim.x + threadIdx.x;
    if (idx >= Ss * 64) return;
    int s = idx >> 6;
    int d = idx & 63;
    float invf = (float)pow(10000.0, -(double)d * (1.0 / 64.0));
    float ang = (float)s * invf;
    float c, sn;
    sincosf(ang, &sn, &c);
    g_cos[idx] = c;
    g_sin[idx] = sn;
}

// ---------------- RoPE apply + fp16 split (Q pair scaled; K single plane) ------
__global__ void rope_split_kernel(const float* __restrict__ q, const float* __restrict__ k,
                                  __half* __restrict__ qh, __half* __restrict__ ql,
                                  __half* __restrict__ kh)
{
    int idx = blockIdx.x * blockDim.x + threadIdx.x;
    if (idx >= Bb * NHh * Ss * 64) return;
    const int d = idx & 63;
    const int s = (idx >> 6) & (Ss - 1);
    const int bh = idx >> 17;
    const int t = (s << 6) + d;
    const float c = g_cos[t];
    const float sn = g_sin[t];
    const float rscale = 0.08838834764831845f;
    const size_t base = ((size_t)bh * Ss + s) * HDd + d;

    float q1 = q[base], q2 = q[base + 64];
    float r1 = (q1 * c - q2 * sn) * rscale;
    float r2 = (q2 * c + q1 * sn) * rscale;
    __half h1 = __float2half_rn(r1);
    __half h2 = __float2half_rn(r2);
    qh[base] = h1; qh[base + 64] = h2;
    ql[base] = __float2half_rn(r1 - __half2float(h1));
    ql[base + 64] = __float2half_rn(r2 - __half2float(h2));

    float k1 = k[base], k2 = k[base + 64];
    kh[base]      = __float2half_rn(k1 * c - k2 * sn);
    kh[base + 64] = __float2half_rn(k2 * c + k1 * sn);
}

// ---------------- fp16 HMMA causal flash attention, BM=128, BN=64 ---------------
// S = (Qh+Ql)*K;  O = (Ph+Pl)*V.  Output: fp16 hi/lo activation [M,H].
#define QsO 0u
#define KsO 65536u
#define VsO 98304u
#define FLASH_SMEM 131072

__global__ __launch_bounds__(256, 1) void flash_mma(
    const __half* __restrict__ qh, const __half* __restrict__ ql,
    const __half* __restrict__ kh, const __half* __restrict__ vh,
    __half* __restrict__ Oh, __half* __restrict__ Ol)
{
    extern __shared__ char smem[];
    const uint32_t sb = smem_u32(smem);
    const int tid = threadIdx.x;
    const int lane = tid & 31;
    const int w = tid >> 5;
    const int qb = (gridDim.x - 1) - blockIdx.x;
    const int bh = blockIdx.y;
    const int b = bh >> 4, h = bh & 15;
    const int qlo = qb * 128;
    const int wr = w * 16;

#pragma unroll
    for (int i = 0; i < 16; i++) {
        int idx = tid + 256 * i;
        int row = idx >> 5;
        int off = (idx & 31) * 16;
        const __half* src = (off < 256)
            ? qh + ((size_t)bh * Ss + qlo + row) * HDd + (off >> 1)
            : ql + ((size_t)bh * Ss + qlo + row) * HDd + ((off - 256) >> 1);
        uint32_t dst = sb + QsO + row * 512 + (off & ~127) + ((off & 127) ^ ((row & 7) << 4));
        CP_ASYNC16(dst, src);
    }
    CP_COMMIT();

#define LOAD_KV(kb_, s_) do {                                                        \
    const int _klo = (kb_) * 64;                                                     \
    _Pragma("unroll")                                                                \
    for (int _i = 0; _i < 4; _i++) {                                                 \
        int _idx = tid + 256 * _i;                                                   \
        int _row = _idx >> 4;                                                        \
        int _off = (_idx & 15) * 16;                                                 \
        const __half* _src = kh + ((size_t)bh * Ss + _klo + _row) * HDd + (_off >> 1); \
        uint32_t _dst = sb + KsO + (s_) * 16384u + _row * 256 + (_off & ~127)        \
                        + ((_off & 127) ^ ((_row & 7) << 4));                        \
        CP_ASYNC16(_dst, _src);                                                      \
    }                                                                                \
    _Pragma("unroll")                                                                \
    for (int _i = 0; _i < 4; _i++) {                                                 \
        int _idx = tid + 256 * _i;                                                   \
        int _row = _idx >> 4;                                                        \
        int _off = (_idx & 15) * 16;                                                 \
        const __half* _src = vh + ((size_t)bh * Ss + _klo + _row) * HDd + (_off >> 1); \
        uint32_t _dst = sb + VsO + (s_) * 16384u + _row * 256 + (_off & ~127)        \
                        + ((_off & 127) ^ ((_row & 7) << 4));                        \
        CP_ASYNC16(_dst, _src);                                                      \
    }                                                                                \
    CP_COMMIT();                                                                     \
} while (0)

    LOAD_KV(0, 0);

    const int a_row = wr + (lane & 15);
    const uint32_t a_base = sb + QsO + a_row * 512;
    const uint32_t a_half = (uint32_t)((lane >> 4) * 16);
    const uint32_t a_xor = (uint32_t)((a_row & 7) * 16);

    const int b_rowk = (lane & 7) + ((lane >> 4) << 3);
    const uint32_t b_halfk = (uint32_t)(((lane >> 3) & 1) * 16);
    const uint32_t b_xork = (uint32_t)((lane & 7) * 16);

    const int v_row = (lane & 7) + (((lane >> 3) & 1) << 3);
    const uint32_t v_half = (uint32_t)((lane >> 4) * 16);
    const uint32_t v_xor = (uint32_t)((lane & 7) * 16);

    float oacc[16][4];
#pragma unroll
    for (int i = 0; i < 16; i++)
#pragma unroll
        for (int q = 0; q < 4; q++) oacc[i][q] = 0.f;
    float m0 = -1e30f, m1 = -1e30f, l0 = 0.f, l1 = 0.f;

    const int row_q0 = qlo + wr + (lane >> 2);
    const int nkb = 2 * qb + 2;

    for (int kb = 0; kb < nkb; kb++) {
        const int klo = kb * 64;
        CP_WAIT0();
        __syncthreads();
        if (kb + 1 < nkb) LOAD_KV(kb + 1, (kb + 1) & 1);

        const bool warp_skip = (klo > qlo + wr + 15);
        if (!warp_skip) {
            const uint32_t kbase = sb + KsO + (uint32_t)(kb & 1) * 16384u;
            const uint32_t vbase = sb + VsO + (uint32_t)(kb & 1) * 16384u;

            float sacc[8][4];
#pragma unroll
            for (int i = 0; i < 8; i++)
#pragma unroll
                for (int q = 0; q < 4; q++) sacc[i][q] = 0.f;

#pragma unroll
            for (int kk = 0; kk < 8; kk++) {
                const uint32_t acol = ((uint32_t)((kk & 3) * 32) + a_half) ^ a_xor;
                const uint32_t achunk = (uint32_t)((kk >> 2) * 128);
                uint32_t ahi[4], alo[4];
                ldsm_x4(ahi, a_base + achunk + acol);
                ldsm_x4(alo, a_base + 256u + achunk + acol);
                const uint32_t bcol = ((uint32_t)((kk & 3) * 32) + b_halfk) ^ b_xork;
#pragma unroll
                for (int g = 0; g < 4; g++) {
                    uint32_t bk[4];
                    ldsm_x4(bk, kbase + (uint32_t)((g * 16 + b_rowk) * 256) + achunk + bcol);
                    mma16816h(sacc[2 * g],     ahi, bk);
                    mma16816h(sacc[2 * g + 1], ahi, bk + 2);
                    mma16816h(sacc[2 * g],     alo, bk);
                    mma16816h(sacc[2 * g + 1], alo, bk + 2);
                }
            }

            if (klo + 63 > qlo + wr) {
#pragma unroll
                for (int nt = 0; nt < 8; nt++) {
                    const int cb = klo + nt * 8 + (lane & 3) * 2;
                    if (cb     > row_q0)     sacc[nt][0] = -1e30f;
                    if (cb + 1 > row_q0)     sacc[nt][1] = -1e30f;
                    if (cb     > row_q0 + 8) sacc[nt][2] = -1e30f;
                    if (cb + 1 > row_q0 + 8) sacc[nt][3] = -1e30f;
                }
            }

            float nm0 = -1e30f, nm1 = -1e30f;
#pragma unroll
            for (int nt = 0; nt < 8; nt++) {
                nm0 = fmaxf(nm0, fmaxf(sacc[nt][0], sacc[nt][1]));
                nm1 = fmaxf(nm1, fmaxf(sacc[nt][2], sacc[nt][3]));
            }
            nm0 = fmaxf(nm0, __shfl_xor_sync(0xffffffffu, nm0, 1));
            nm0 = fmaxf(nm0, __shfl_xor_sync(0xffffffffu, nm0, 2));
            nm1 = fmaxf(nm1, __shfl_xor_sync(0xffffffffu, nm1, 1));
            nm1 = fmaxf(nm1, __shfl_xor_sync(0xffffffffu, nm1, 2));
            nm0 = fmaxf(m0, nm0);
            nm1 = fmaxf(m1, nm1);
            const float alpha0 = __expf(m0 - nm0);
            const float alpha1 = __expf(m1 - nm1);
            m0 = nm0; m1 = nm1;

            uint32_t phi[8][2], plo[8][2];
            float s0 = 0.f, s1 = 0.f;
#pragma unroll
            for (int nt = 0; nt < 8; nt++) {
                float p00 = __expf(sacc[nt][0] - m0);
                float p01 = __expf(sacc[nt][1] - m0);
                float p10 = __expf(sacc[nt][2] - m1);
                float p11 = __expf(sacc[nt][3] - m1);
                s0 += p00 + p01;
                s1 += p10 + p11;
                __half2 h0 = __floats2half2_rn(p00, p01);
                __half2 h1 = __floats2half2_rn(p10, p11);
                phi[nt][0] = *(uint32_t*)&h0;
                phi[nt][1] = *(uint32_t*)&h1;
                float2 f0 = __half22float2(h0);
                float2 f1 = __half22float2(h1);
                __half2 e0 = __floats2half2_rn(p00 - f0.x, p01 - f0.y);
                __half2 e1 = __floats2half2_rn(p10 - f1.x, p11 - f1.y);
                plo[nt][0] = *(uint32_t*)&e0;
                plo[nt][1] = *(uint32_t*)&e1;
            }
            s0 += __shfl_xor_sync(0xffffffffu, s0, 1);
            s0 += __shfl_xor_sync(0xffffffffu, s0, 2);
            s1 += __shfl_xor_sync(0xffffffffu, s1, 1);
            s1 += __shfl_xor_sync(0xffffffffu, s1, 2);
            l0 = l0 * alpha0 + s0;
            l1 = l1 * alpha1 + s1;
#pragma unroll
            for (int dt = 0; dt < 16; dt++) {
                oacc[dt][0] *= alpha0; oacc[dt][1] *= alpha0;
                oacc[dt][2] *= alpha1; oacc[dt][3] *= alpha1;
            }

#pragma unroll
            for (int jt = 0; jt < 4; jt++) {
                uint32_t ah[4] = { phi[2 * jt][0], phi[2 * jt][1],
                                   phi[2 * jt + 1][0], phi[2 * jt + 1][1] };
                uint32_t al[4] = { plo[2 * jt][0], plo[2 * jt][1],
                                   plo[2 * jt + 1][0], plo[2 * jt + 1][1] };
                const uint32_t vrow = (uint32_t)((jt * 16 + v_row) * 256);
#pragma unroll
                for (int g = 0; g < 8; g++) {
                    const uint32_t colb = (uint32_t)(g * 32) + v_half;
                    const uint32_t voff = vrow + (colb & ~127u) + ((colb & 127u) ^ v_xor);
                    uint32_t bv[4];
                    ldsm_x4_t(bv, vbase + voff);
                    mma16816h(oacc[2 * g],     ah, bv);
                    mma16816h(oacc[2 * g + 1], ah, bv + 2);
                    mma16816h(oacc[2 * g],     al, bv);
                    mma16816h(oacc[2 * g + 1], al, bv + 2);
                }
            }
        }
        __syncthreads();
    }

    // epilogue: normalize + fp16 hi/lo split straight into activation buffers
    const float inv0 = 1.f / l0;
    const float inv1 = 1.f / l1;
    const int col0 = h * HDd + (lane & 3) * 2;
    const size_t base0 = ((size_t)b * Ss + row_q0) * Hh + col0;
    const size_t base1 = ((size_t)b * Ss + row_q0 + 8) * Hh + col0;
#pragma unroll
    for (int dt = 0; dt < 16; dt++) {
        float v00 = oacc[dt][0] * inv0, v01 = oacc[dt][1] * inv0;
        float v10 = oacc[dt][2] * inv1, v11 = oacc[dt][3] * inv1;
        __half2 h0 = __floats2half2_rn(v00, v01);
        __half2 h1 = __floats2half2_rn(v10, v11);
        float2 f0 = __half22float2(h0);
        float2 f1 = __half22float2(h1);
        __half2 e0 = __floats2half2_rn(v00 - f0.x, v01 - f0.y);
        __half2 e1 = __floats2half2_rn(v10 - f1.x, v11 - f1.y);
        *(__half2*)(Oh + base0 + dt * 8) = h0;
        *(__half2*)(Ol + base0 + dt * 8) = e0;
        *(__half2*)(Oh + base1 + dt * 8) = h1;
        *(__half2*)(Ol + base1 + dt * 8) = e1;
    }
#undef LOAD_KV
}

// ---------------- launch ----------------
extern "C" void kernel_launch(void* const* d_in, const int* in_sizes, int n_in,
                              void* d_out, int out_size)
{
    (void)in_sizes; (void)n_in; (void)out_size;
    const float* hs = (const float*)d_in[0];
    const float* qw = (const float*)d_in[1];
    const float* kw = (const float*)d_in[2];
    const float* vw = (const float*)d_in[3];
    const float* ow = (const float*)d_in[4];
    float* out = (float*)d_out;

    float *qbuf, *kbuf;
    __half *ah, *al, *wgt, *qh, *ql, *kh, *vh;
    cudaGetSymbolAddress((void**)&qbuf, g_q);
    cudaGetSymbolAddress((void**)&kbuf, g_k);
    cudaGetSymbolAddress((void**)&ah, g_ah);
    cudaGetSymbolAddress((void**)&al, g_al);
    cudaGetSymbolAddress((void**)&wgt, g_w);
    cudaGetSymbolAddress((void**)&qh, g_qh);
    cudaGetSymbolAddress((void**)&ql, g_ql);
    cudaGetSymbolAddress((void**)&kh, g_kh);
    cudaGetSymbolAddress((void**)&vh, g_vh);
    const size_t WSZ = (size_t)Hh * GK;

    const int gemm_smem = 98304;  // 4 stages x 24KB
    cudaFuncSetAttribute(gemm2p<0>, cudaFuncAttributeMaxDynamicSharedMemorySize, gemm_smem);
    cudaFuncSetAttribute(gemm2p<1>, cudaFuncAttributeMaxDynamicSharedMemorySize, gemm_smem);
    cudaFuncSetAttribute(gemm2p<2>, cudaFuncAttributeMaxDynamicSharedMemorySize, gemm_smem);
    cudaFuncSetAttribute(flash_mma, cudaFuncAttributeMaxDynamicSharedMemorySize, FLASH_SMEM);

    const dim3 gGemm(Hh / 128, Mm / 128);  // (16, 32) = 512 CTAs, 2/SM
    const int actN = Mm * Hh;
    const int wN = Hh * Hh;

    split_pair_half<<<(actN + 255) / 256, 256>>>(hs, ah, al, actN);
    convert_w4<<<dim3((wN + 255) / 256, 4), 256>>>(qw, kw, vw, ow, wgt);
    rope_tables_kernel<<<(Ss * 64 + 255) / 256, 256>>>();

    gemm2p<1><<<gGemm, 128, gemm_smem>>>(ah, al, wgt, qbuf);
    gemm2p<1><<<gGemm, 128, gemm_smem>>>(ah, al, wgt + WSZ, kbuf);
    gemm2p<2><<<gGemm, 128, gemm_smem>>>(ah, al, wgt + 2 * WSZ, vh);

    rope_split_kernel<<<(Bb * NHh * Ss * 64 + 255) / 256, 256>>>(qbuf, kbuf, qh, ql, kh);

    // flash overwrites ah/al with the attention-output activation (fp16 hi/lo)
    flash_mma<<<dim3(Ss / 128, Bb * NHh), 256, FLASH_SMEM>>>(qh, ql, kh, vh, ah, al);

    gemm2p<0><<<gGemm, 128, gemm_smem>>>(ah, al, wgt + 3 * WSZ, out);
}

// round 9
// speedup vs baseline: 1.5640x; 1.0499x over previous
#include <cuda_runtime.h>
#include <cuda_bf16.h>
#include <cuda_fp16.h>
#include <math.h>
#include <stdint.h>

#define Bb 2
#define Ss 2048
#define Hh 2048
#define NHh 16
#define HDd 128
#define Mm (Bb*Ss)
#define GK 2048
#define GCH 32
#define GNCH (GK/GCH)      // 64

// ---------------- scratch ----------------
__device__ float g_cos[Ss*64];
__device__ float g_sin[Ss*64];
__device__ __half g_ah[(size_t)Mm*GK];         // activation hi (fp16)
__device__ __half g_al[(size_t)Mm*GK];         // activation lo (fp16)
__device__ __half g_w[4][(size_t)Hh*GK];       // weights fp16 (q,k,v,o)
// flash fp16 operands
__device__ __half g_qh[(size_t)Bb*NHh*Ss*HDd];
__device__ __half g_ql[(size_t)Bb*NHh*Ss*HDd];
__device__ __half g_kh[(size_t)Bb*NHh*Ss*HDd];
__device__ __half g_vh[(size_t)Bb*NHh*Ss*HDd];

// ---------------- PTX helpers ----------------
__device__ __forceinline__ uint32_t smem_u32(const void* p) {
    uint32_t a;
    asm("{ .reg .u64 t; cvta.to.shared.u64 t, %1; cvt.u32.u64 %0, t; }" : "=r"(a) : "l"(p));
    return a;
}
#define CP_ASYNC16(sa, gp) \
    asm volatile("cp.async.cg.shared.global [%0], [%1], 16;" :: "r"(sa), "l"(gp) : "memory")
#define CP_COMMIT() asm volatile("cp.async.commit_group;" ::: "memory")
#define CP_WAIT0()  asm volatile("cp.async.wait_group 0;" ::: "memory")
#define CP_WAIT1()  asm volatile("cp.async.wait_group 1;" ::: "memory")
#define CP_WAIT2()  asm volatile("cp.async.wait_group 2;" ::: "memory")

__device__ __forceinline__ void ldsm_x4(uint32_t* r, uint32_t addr) {
    asm volatile("ldmatrix.sync.aligned.m8n8.x4.shared.b16 {%0,%1,%2,%3}, [%4];"
        : "=r"(r[0]), "=r"(r[1]), "=r"(r[2]), "=r"(r[3]) : "r"(addr));
}
__device__ __forceinline__ void ldsm_x4_t(uint32_t* r, uint32_t addr) {
    asm volatile("ldmatrix.sync.aligned.m8n8.x4.trans.shared.b16 {%0,%1,%2,%3}, [%4];"
        : "=r"(r[0]), "=r"(r[1]), "=r"(r[2]), "=r"(r[3]) : "r"(addr));
}
__device__ __forceinline__ void mma16816h(float* d, const uint32_t* a, const uint32_t* b) {
    asm volatile("mma.sync.aligned.m16n8k16.row.col.f32.f16.f16.f32 "
        "{%0,%1,%2,%3}, {%4,%5,%6,%7}, {%8,%9}, {%0,%1,%2,%3};"
        : "+f"(d[0]), "+f"(d[1]), "+f"(d[2]), "+f"(d[3])
        : "r"(a[0]), "r"(a[1]), "r"(a[2]), "r"(a[3]), "r"(b[0]), "r"(b[1]));
}
#define SWZ32(o) ((o) ^ (((o) >> 3) & 0x30))

// ---------------- fp16 hi/lo pair split (activations) ----------------
__global__ void split_pair_half(const float* __restrict__ X,
                                __half* __restrict__ Xh,
                                __half* __restrict__ Xl, int n)
{
    int idx = blockIdx.x * blockDim.x + threadIdx.x;
    if (idx >= n) return;
    float x = X[idx];
    __half hi = __float2half_rn(x);
    Xh[idx] = hi;
    Xl[idx] = __float2half_rn(x - __half2float(hi));
}

// ---------------- all-4 weight fp16 converts in one launch ----------------
__global__ void convert_w4(const float* __restrict__ w0, const float* __restrict__ w1,
                           const float* __restrict__ w2, const float* __restrict__ w3,
                           __half* __restrict__ H)
{
    int idx = blockIdx.x * blockDim.x + threadIdx.x;
    const int t = blockIdx.y;
    if (idx >= Hh * Hh) return;
    const float* W = (t == 0) ? w0 : (t == 1) ? w1 : (t == 2) ? w2 : w3;
    H[(size_t)t * Hh * GK + idx] = __float2half_rn(W[idx]);
}

// ---------------- RoPE tables ----------------
__global__ void rope_tables_kernel()
{
    int idx = blockIdx.x * blockDim.x + threadIdx.x;
    if (idx >= Ss * 64) return;
    int s = idx >> 6;
    int d = idx & 63;
    float invf = (float)pow(10000.0, -(double)d * (1.0 / 64.0));
    float ang = (float)s * invf;
    float c, sn;
    sincosf(ang, &sn, &c);
    g_cos[idx] = c;
    g_sin[idx] = sn;
}

// ---------------- shared GEMM mainloop pieces ----------------
#define STG2 24576u
#define AhO2 0u
#define AlO2 8192u
#define BO2  16384u

#define GEMM_LOAD_STAGE(ci, st) do {                                                \
    const int _k0 = (ci) * GCH;                                                     \
    const uint32_t _bs = sb + (uint32_t)(st) * STG2;                                \
    _Pragma("unroll")                                                               \
    for (int _i = 0; _i < 4; _i++) {                                                \
        int _idx = tid + 128 * _i;                                                  \
        int _r = _idx >> 2;                                                         \
        int _cb = (_idx & 3) * 16;                                                  \
        CP_ASYNC16(_bs + AhO2 + SWZ32(_r * 64 + _cb),                               \
                   Ah + (size_t)(m0 + _r) * GK + _k0 + (_cb >> 1));                 \
    }                                                                               \
    _Pragma("unroll")                                                               \
    for (int _i = 0; _i < 4; _i++) {                                                \
        int _idx = tid + 128 * _i;                                                  \
        int _r = _idx >> 2;                                                         \
        int _cb = (_idx & 3) * 16;                                                  \
        CP_ASYNC16(_bs + AlO2 + SWZ32(_r * 64 + _cb),                               \
                   Al + (size_t)(m0 + _r) * GK + _k0 + (_cb >> 1));                 \
    }                                                                               \
    _Pragma("unroll")                                                               \
    for (int _i = 0; _i < 4; _i++) {                                                \
        int _idx = tid + 128 * _i;                                                  \
        int _r = _idx >> 2;                                                         \
        int _cb = (_idx & 3) * 16;                                                  \
        CP_ASYNC16(_bs + BO2 + SWZ32(_r * 64 + _cb),                                \
                   Bw + (size_t)(n0 + _r) * GK + _k0 + (_cb >> 1));                 \
    }                                                                               \
    CP_COMMIT();                                                                    \
} while (0)

#define GEMM_MAINLOOP()                                                             \
    const uint32_t a_half = (uint32_t)((lane >> 4) * 16);                           \
    const uint32_t a_xor = (uint32_t)((((lane & 15) >> 1) & 3) * 16);               \
    uint32_t aRow[4];                                                               \
    _Pragma("unroll")                                                               \
    for (int mi = 0; mi < 4; mi++)                                                  \
        aRow[mi] = (uint32_t)((wm * 64 + mi * 16 + (lane & 15)) * 64);              \
    const int b_lrow = (lane & 7) + ((lane >> 4) << 3);                             \
    const uint32_t b_half = (uint32_t)(((lane >> 3) & 1) * 16);                     \
    const uint32_t b_xor = (uint32_t)((((lane & 7) >> 1) & 3) * 16);                \
    uint32_t bRow[4];                                                               \
    _Pragma("unroll")                                                               \
    for (int nt = 0; nt < 4; nt++)                                                  \
        bRow[nt] = (uint32_t)((wn * 64 + nt * 16 + b_lrow) * 64);                   \
    GEMM_LOAD_STAGE(0, 0);                                                          \
    GEMM_LOAD_STAGE(1, 1);                                                          \
    GEMM_LOAD_STAGE(2, 2);                                                          \
    for (int c = 0; c < GNCH; c++) {                                                \
        if (c <= GNCH - 3) CP_WAIT2();                                              \
        else if (c == GNCH - 2) CP_WAIT1();                                         \
        else CP_WAIT0();                                                            \
        __syncthreads();                                                            \
        if (c + 3 < GNCH) GEMM_LOAD_STAGE(c + 3, (c + 3) & 3);                      \
        const uint32_t bs = sb + (uint32_t)(c & 3) * STG2;                          \
        _Pragma("unroll")                                                           \
        for (int kk = 0; kk < 2; kk++) {                                            \
            const uint32_t acol = ((uint32_t)(kk * 32) + a_half) ^ a_xor;           \
            const uint32_t bcol = ((uint32_t)(kk * 32) + b_half) ^ b_xor;           \
            uint32_t ah4[4][4], b4[4][4], al4[4][4];                                \
            _Pragma("unroll")                                                       \
            for (int mi = 0; mi < 4; mi++)                                          \
                ldsm_x4(ah4[mi], bs + AhO2 + aRow[mi] + acol);                      \
            _Pragma("unroll")                                                       \
            for (int nt = 0; nt < 4; nt++)                                          \
                ldsm_x4(b4[nt], bs + BO2 + bRow[nt] + bcol);                        \
            _Pragma("unroll")                                                       \
            for (int mi = 0; mi < 4; mi++)                                          \
                _Pragma("unroll")                                                   \
                for (int nt = 0; nt < 4; nt++) {                                    \
                    mma16816h(acc[mi][2 * nt],     ah4[mi], b4[nt]);                \
                    mma16816h(acc[mi][2 * nt + 1], ah4[mi], b4[nt] + 2);            \
                }                                                                   \
            _Pragma("unroll")                                                       \
            for (int mi = 0; mi < 4; mi++)                                          \
                ldsm_x4(al4[mi], bs + AlO2 + aRow[mi] + acol);                      \
            _Pragma("unroll")                                                       \
            for (int mi = 0; mi < 4; mi++)                                          \
                _Pragma("unroll")                                                   \
                for (int nt = 0; nt < 4; nt++) {                                    \
                    mma16816h(acc[mi][2 * nt],     al4[mi], b4[nt]);                \
                    mma16816h(acc[mi][2 * nt + 1], al4[mi], b4[nt] + 2);            \
                }                                                                   \
        }                                                                           \
    }

// ---------------- fused QKV GEMM: blockIdx.z = 0(Q rope), 1(K rope), 2(V) -------
__global__ __launch_bounds__(128, 2) void qkv_gemm(const __half* __restrict__ Ah,
                                                   const __half* __restrict__ Al,
                                                   const __half* __restrict__ Wg,
                                                   __half* __restrict__ qh,
                                                   __half* __restrict__ ql,
                                                   __half* __restrict__ kh,
                                                   __half* __restrict__ vh)
{
    extern __shared__ char smem[];
    const uint32_t sb = smem_u32(smem);
    const int tid = threadIdx.x;
    const int wid = tid >> 5;
    const int lane = tid & 31;
    const int n0 = blockIdx.x * 128;
    const int m0 = blockIdx.y * 128;
    const int z = blockIdx.z;
    const int wm = wid & 1;
    const int wn = wid >> 1;
    const __half* Bw = Wg + (size_t)z * Hh * GK;

    float acc[4][8][4];
#pragma unroll
    for (int mi = 0; mi < 4; mi++)
#pragma unroll
        for (int ni = 0; ni < 8; ni++)
#pragma unroll
            for (int q = 0; q < 4; q++) acc[mi][ni][q] = 0.f;

    GEMM_MAINLOOP();

    const int er = lane >> 2;
    const int ec = (lane & 3) * 2;

    if (z == 2) {
        // V: direct fp16 head scatter
#pragma unroll
        for (int mi = 0; mi < 4; mi++) {
#pragma unroll
            for (int ni = 0; ni < 8; ni++) {
                const int m = m0 + wm * 64 + mi * 16 + er;
                const int n = n0 + wn * 64 + ni * 8 + ec;
                const int b_ = m >> 11;
                const int s_ = m & (Ss - 1);
                const int h_ = n >> 7;
                const int d_ = n & (HDd - 1);
                const size_t o0 = (((size_t)b_ * NHh + h_) * Ss + s_) * HDd + d_;
                *(__half2*)(vh + o0) = __floats2half2_rn(acc[mi][ni][0], acc[mi][ni][1]);
                *(__half2*)(vh + o0 + 8 * HDd) = __floats2half2_rn(acc[mi][ni][2], acc[mi][ni][3]);
            }
        }
        return;
    }

    // Q/K: stage fp32 tile through smem, apply RoPE, emit fp16 (hi/lo for Q)
    __syncthreads();   // all warps done reading pipeline smem
    float* Cs = (float*)smem;   // [128][130] pitch
#pragma unroll
    for (int mi = 0; mi < 4; mi++) {
#pragma unroll
        for (int ni = 0; ni < 8; ni++) {
            const int rr = wm * 64 + mi * 16 + er;
            const int cc = wn * 64 + ni * 8 + ec;
            Cs[rr * 130 + cc]           = acc[mi][ni][0];
            Cs[rr * 130 + cc + 1]       = acc[mi][ni][1];
            Cs[(rr + 8) * 130 + cc]     = acc[mi][ni][2];
            Cs[(rr + 8) * 130 + cc + 1] = acc[mi][ni][3];
        }
    }
    __syncthreads();

    const int d = tid & 63;
    const int rg = tid >> 6;              // row group 0/1
    const int b_ = blockIdx.y >> 4;       // m0/2048
    const int h_ = blockIdx.x;
    const int s0 = m0 & (Ss - 1);
    const float rsc = 0.08838834764831845f;

    for (int rr = rg * 64; rr < rg * 64 + 64; rr++) {
        const int s = s0 + rr;
        const float x1 = Cs[rr * 130 + d];
        const float x2 = Cs[rr * 130 + d + 64];
        const float c = g_cos[s * 64 + d];
        const float sn = g_sin[s * 64 + d];
        float r1 = x1 * c - x2 * sn;
        float r2 = x2 * c + x1 * sn;
        const size_t ob = (((size_t)b_ * NHh + h_) * Ss + s) * HDd + d;
        if (z == 0) {
            r1 *= rsc; r2 *= rsc;
            const __half h1 = __float2half_rn(r1);
            const __half h2 = __float2half_rn(r2);
            qh[ob] = h1;
            qh[ob + 64] = h2;
            ql[ob] = __float2half_rn(r1 - __half2float(h1));
            ql[ob + 64] = __float2half_rn(r2 - __half2float(h2));
        } else {
            kh[ob] = __float2half_rn(r1);
            kh[ob + 64] = __float2half_rn(r2);
        }
    }
}

// ---------------- O GEMM: fp32 row-major out ----------------
__global__ __launch_bounds__(128, 2) void o_gemm(const __half* __restrict__ Ah,
                                                 const __half* __restrict__ Al,
                                                 const __half* __restrict__ Bw,
                                                 float* __restrict__ C)
{
    extern __shared__ char smem[];
    const uint32_t sb = smem_u32(smem);
    const int tid = threadIdx.x;
    const int wid = tid >> 5;
    const int lane = tid & 31;
    const int n0 = blockIdx.x * 128;
    const int m0 = blockIdx.y * 128;
    const int wm = wid & 1;
    const int wn = wid >> 1;

    float acc[4][8][4];
#pragma unroll
    for (int mi = 0; mi < 4; mi++)
#pragma unroll
        for (int ni = 0; ni < 8; ni++)
#pragma unroll
            for (int q = 0; q < 4; q++) acc[mi][ni][q] = 0.f;

    GEMM_MAINLOOP();

    const int er = lane >> 2;
    const int ec = (lane & 3) * 2;
#pragma unroll
    for (int mi = 0; mi < 4; mi++) {
#pragma unroll
        for (int ni = 0; ni < 8; ni++) {
            const int m = m0 + wm * 64 + mi * 16 + er;
            const int n = n0 + wn * 64 + ni * 8 + ec;
            *(float2*)(C + (size_t)m * Hh + n) =
                make_float2(acc[mi][ni][0], acc[mi][ni][1]);
            *(float2*)(C + (size_t)(m + 8) * Hh + n) =
                make_float2(acc[mi][ni][2], acc[mi][ni][3]);
        }
    }
}

// ---------------- fp16 HMMA causal flash attention, BM=128, BN=64 ---------------
#define QsO 0u
#define KsO 65536u
#define VsO 98304u
#define FLASH_SMEM 131072

__global__ __launch_bounds__(256, 1) void flash_mma(
    const __half* __restrict__ qh, const __half* __restrict__ ql,
    const __half* __restrict__ kh, const __half* __restrict__ vh,
    __half* __restrict__ Oh, __half* __restrict__ Ol)
{
    extern __shared__ char smem[];
    const uint32_t sb = smem_u32(smem);
    const int tid = threadIdx.x;
    const int lane = tid & 31;
    const int w = tid >> 5;
    const int qb = (gridDim.x - 1) - blockIdx.x;
    const int bh = blockIdx.y;
    const int b = bh >> 4, h = bh & 15;
    const int qlo = qb * 128;
    const int wr = w * 16;

#pragma unroll
    for (int i = 0; i < 16; i++) {
        int idx = tid + 256 * i;
        int row = idx >> 5;
        int off = (idx & 31) * 16;
        const __half* src = (off < 256)
            ? qh + ((size_t)bh * Ss + qlo + row) * HDd + (off >> 1)
            : ql + ((size_t)bh * Ss + qlo + row) * HDd + ((off - 256) >> 1);
        uint32_t dst = sb + QsO + row * 512 + (off & ~127) + ((off & 127) ^ ((row & 7) << 4));
        CP_ASYNC16(dst, src);
    }
    CP_COMMIT();

#define LOAD_KV(kb_, s_) do {                                                        \
    const int _klo = (kb_) * 64;                                                     \
    _Pragma("unroll")                                                                \
    for (int _i = 0; _i < 4; _i++) {                                                 \
        int _idx = tid + 256 * _i;                                                   \
        int _row = _idx >> 4;                                                        \
        int _off = (_idx & 15) * 16;                                                 \
        const __half* _src = kh + ((size_t)bh * Ss + _klo + _row) * HDd + (_off >> 1); \
        uint32_t _dst = sb + KsO + (s_) * 16384u + _row * 256 + (_off & ~127)        \
                        + ((_off & 127) ^ ((_row & 7) << 4));                        \
        CP_ASYNC16(_dst, _src);                                                      \
    }                                                                                \
    _Pragma("unroll")                                                                \
    for (int _i = 0; _i < 4; _i++) {                                                 \
        int _idx = tid + 256 * _i;                                                   \
        int _row = _idx >> 4;                                                        \
        int _off = (_idx & 15) * 16;                                                 \
        const __half* _src = vh + ((size_t)bh * Ss + _klo + _row) * HDd + (_off >> 1); \
        uint32_t _dst = sb + VsO + (s_) * 16384u + _row * 256 + (_off & ~127)        \
                        + ((_off & 127) ^ ((_row & 7) << 4));                        \
        CP_ASYNC16(_dst, _src);                                                      \
    }                                                                                \
    CP_COMMIT();                                                                     \
} while (0)

    LOAD_KV(0, 0);

    const int a_row = wr + (lane & 15);
    const uint32_t a_base = sb + QsO + a_row * 512;
    const uint32_t a_half = (uint32_t)((lane >> 4) * 16);
    const uint32_t a_xor = (uint32_t)((a_row & 7) * 16);

    const int b_rowk = (lane & 7) + ((lane >> 4) << 3);
    const uint32_t b_halfk = (uint32_t)(((lane >> 3) & 1) * 16);
    const uint32_t b_xork = (uint32_t)((lane & 7) * 16);

    const int v_row = (lane & 7) + (((lane >> 3) & 1) << 3);
    const uint32_t v_half = (uint32_t)((lane >> 4) * 16);
    const uint32_t v_xor = (uint32_t)((lane & 7) * 16);

    float oacc[16][4];
#pragma unroll
    for (int i = 0; i < 16; i++)
#pragma unroll
        for (int q = 0; q < 4; q++) oacc[i][q] = 0.f;
    float m0 = -1e30f, m1 = -1e30f, l0 = 0.f, l1 = 0.f;

    const int row_q0 = qlo + wr + (lane >> 2);
    const int nkb = 2 * qb + 2;

    for (int kb = 0; kb < nkb; kb++) {
        const int klo = kb * 64;
        CP_WAIT0();
        __syncthreads();
        if (kb + 1 < nkb) LOAD_KV(kb + 1, (kb + 1) & 1);

        const bool warp_skip = (klo > qlo + wr + 15);
        if (!warp_skip) {
            const uint32_t kbase = sb + KsO + (uint32_t)(kb & 1) * 16384u;
            const uint32_t vbase = sb + VsO + (uint32_t)(kb & 1) * 16384u;

            float sacc[8][4];
#pragma unroll
            for (int i = 0; i < 8; i++)
#pragma unroll
                for (int q = 0; q < 4; q++) sacc[i][q] = 0.f;

#pragma unroll
            for (int kk = 0; kk < 8; kk++) {
                const uint32_t acol = ((uint32_t)((kk & 3) * 32) + a_half) ^ a_xor;
                const uint32_t achunk = (uint32_t)((kk >> 2) * 128);
                uint32_t ahi[4], alo[4];
                ldsm_x4(ahi, a_base + achunk + acol);
                ldsm_x4(alo, a_base + 256u + achunk + acol);
                const uint32_t bcol = ((uint32_t)((kk & 3) * 32) + b_halfk) ^ b_xork;
#pragma unroll
                for (int g = 0; g < 4; g++) {
                    uint32_t bk[4];
                    ldsm_x4(bk, kbase + (uint32_t)((g * 16 + b_rowk) * 256) + achunk + bcol);
                    mma16816h(sacc[2 * g],     ahi, bk);
                    mma16816h(sacc[2 * g + 1], ahi, bk + 2);
                    mma16816h(sacc[2 * g],     alo, bk);
                    mma16816h(sacc[2 * g + 1], alo, bk + 2);
                }
            }

            if (klo + 63 > qlo + wr) {
#pragma unroll
                for (int nt = 0; nt < 8; nt++) {
                    const int cb = klo + nt * 8 + (lane & 3) * 2;
                    if (cb     > row_q0)     sacc[nt][0] = -1e30f;
                    if (cb + 1 > row_q0)     sacc[nt][1] = -1e30f;
                    if (cb     > row_q0 + 8) sacc[nt][2] = -1e30f;
                    if (cb + 1 > row_q0 + 8) sacc[nt][3] = -1e30f;
                }
            }

            float nm0 = -1e30f, nm1 = -1e30f;
#pragma unroll
            for (int nt = 0; nt < 8; nt++) {
                nm0 = fmaxf(nm0, fmaxf(sacc[nt][0], sacc[nt][1]));
                nm1 = fmaxf(nm1, fmaxf(sacc[nt][2], sacc[nt][3]));
            }
            nm0 = fmaxf(nm0, __shfl_xor_sync(0xffffffffu, nm0, 1));
            nm0 = fmaxf(nm0, __shfl_xor_sync(0xffffffffu, nm0, 2));
            nm1 = fmaxf(nm1, __shfl_xor_sync(0xffffffffu, nm1, 1));
            nm1 = fmaxf(nm1, __shfl_xor_sync(0xffffffffu, nm1, 2));
            nm0 = fmaxf(m0, nm0);
            nm1 = fmaxf(m1, nm1);
            const float alpha0 = __expf(m0 - nm0);
            const float alpha1 = __expf(m1 - nm1);
            m0 = nm0; m1 = nm1;

            uint32_t phi[8][2], plo[8][2];
            float s0 = 0.f, s1 = 0.f;
#pragma unroll
            for (int nt = 0; nt < 8; nt++) {
                float p00 = __expf(sacc[nt][0] - m0);
                float p01 = __expf(sacc[nt][1] - m0);
                float p10 = __expf(sacc[nt][2] - m1);
                float p11 = __expf(sacc[nt][3] - m1);
                s0 += p00 + p01;
                s1 += p10 + p11;
                __half2 h0 = __floats2half2_rn(p00, p01);
                __half2 h1 = __floats2half2_rn(p10, p11);
                phi[nt][0] = *(uint32_t*)&h0;
                phi[nt][1] = *(uint32_t*)&h1;
                float2 f0 = __half22float2(h0);
                float2 f1 = __half22float2(h1);
                __half2 e0 = __floats2half2_rn(p00 - f0.x, p01 - f0.y);
                __half2 e1 = __floats2half2_rn(p10 - f1.x, p11 - f1.y);
                plo[nt][0] = *(uint32_t*)&e0;
                plo[nt][1] = *(uint32_t*)&e1;
            }
            s0 += __shfl_xor_sync(0xffffffffu, s0, 1);
            s0 += __shfl_xor_sync(0xffffffffu, s0, 2);
            s1 += __shfl_xor_sync(0xffffffffu, s1, 1);
            s1 += __shfl_xor_sync(0xffffffffu, s1, 2);
            l0 = l0 * alpha0 + s0;
            l1 = l1 * alpha1 + s1;
#pragma unroll
            for (int dt = 0; dt < 16; dt++) {
                oacc[dt][0] *= alpha0; oacc[dt][1] *= alpha0;
                oacc[dt][2] *= alpha1; oacc[dt][3] *= alpha1;
            }

#pragma unroll
            for (int jt = 0; jt < 4; jt++) {
                uint32_t ah[4] = { phi[2 * jt][0], phi[2 * jt][1],
                                   phi[2 * jt + 1][0], phi[2 * jt + 1][1] };
                uint32_t al[4] = { plo[2 * jt][0], plo[2 * jt][1],
                                   plo[2 * jt + 1][0], plo[2 * jt + 1][1] };
                const uint32_t vrow = (uint32_t)((jt * 16 + v_row) * 256);
#pragma unroll
                for (int g = 0; g < 8; g++) {
                    const uint32_t colb = (uint32_t)(g * 32) + v_half;
                    const uint32_t voff = vrow + (colb & ~127u) + ((colb & 127u) ^ v_xor);
                    uint32_t bv[4];
                    ldsm_x4_t(bv, vbase + voff);
                    mma16816h(oacc[2 * g],     ah, bv);
                    mma16816h(oacc[2 * g + 1], ah, bv + 2);
                    mma16816h(oacc[2 * g],     al, bv);
                    mma16816h(oacc[2 * g + 1], al, bv + 2);
                }
            }
        }
        __syncthreads();
    }

    const float inv0 = 1.f / l0;
    const float inv1 = 1.f / l1;
    const int col0 = h * HDd + (lane & 3) * 2;
    const size_t base0 = ((size_t)b * Ss + row_q0) * Hh + col0;
    const size_t base1 = ((size_t)b * Ss + row_q0 + 8) * Hh + col0;
#pragma unroll
    for (int dt = 0; dt < 16; dt++) {
        float v00 = oacc[dt][0] * inv0, v01 = oacc[dt][1] * inv0;
        float v10 = oacc[dt][2] * inv1, v11 = oacc[dt][3] * inv1;
        __half2 h0 = __floats2half2_rn(v00, v01);
        __half2 h1 = __floats2half2_rn(v10, v11);
        float2 f0 = __half22float2(h0);
        float2 f1 = __half22float2(h1);
        __half2 e0 = __floats2half2_rn(v00 - f0.x, v01 - f0.y);
        __half2 e1 = __floats2half2_rn(v10 - f1.x, v11 - f1.y);
        *(__half2*)(Oh + base0 + dt * 8) = h0;
        *(__half2*)(Ol + base0 + dt * 8) = e0;
        *(__half2*)(Oh + base1 + dt * 8) = h1;
        *(__half2*)(Ol + base1 + dt * 8) = e1;
    }
#undef LOAD_KV
}

// ---------------- launch ----------------
extern "C" void kernel_launch(void* const* d_in, const int* in_sizes, int n_in,
                              void* d_out, int out_size)
{
    (void)in_sizes; (void)n_in; (void)out_size;
    const float* hs = (const float*)d_in[0];
    const float* qw = (const float*)d_in[1];
    const float* kw = (const float*)d_in[2];
    const float* vw = (const float*)d_in[3];
    const float* ow = (const float*)d_in[4];
    float* out = (float*)d_out;

    __half *ah, *al, *wgt, *qh, *ql, *kh, *vh;
    cudaGetSymbolAddress((void**)&ah, g_ah);
    cudaGetSymbolAddress((void**)&al, g_al);
    cudaGetSymbolAddress((void**)&wgt, g_w);
    cudaGetSymbolAddress((void**)&qh, g_qh);
    cudaGetSymbolAddress((void**)&ql, g_ql);
    cudaGetSymbolAddress((void**)&kh, g_kh);
    cudaGetSymbolAddress((void**)&vh, g_vh);
    const size_t WSZ = (size_t)Hh * GK;

    const int gemm_smem = 98304;  // 4 stages x 24KB (also covers 66.5KB epilogue tile)
    cudaFuncSetAttribute(qkv_gemm, cudaFuncAttributeMaxDynamicSharedMemorySize, gemm_smem);
    cudaFuncSetAttribute(o_gemm, cudaFuncAttributeMaxDynamicSharedMemorySize, gemm_smem);
    cudaFuncSetAttribute(flash_mma, cudaFuncAttributeMaxDynamicSharedMemorySize, FLASH_SMEM);

    const int actN = Mm * Hh;
    const int wN = Hh * Hh;

    split_pair_half<<<(actN + 255) / 256, 256>>>(hs, ah, al, actN);
    convert_w4<<<dim3((wN + 255) / 256, 4), 256>>>(qw, kw, vw, ow, wgt);
    rope_tables_kernel<<<(Ss * 64 + 255) / 256, 256>>>();

    // fused Q/K/V projections (+ RoPE + fp16 splits in epilogue)
    qkv_gemm<<<dim3(Hh / 128, Mm / 128, 3), 128, gemm_smem>>>(ah, al, wgt,
                                                              qh, ql, kh, vh);

    // flash overwrites ah/al with the attention-output activation (fp16 hi/lo)
    flash_mma<<<dim3(Ss / 128, Bb * NHh), 256, FLASH_SMEM>>>(qh, ql, kh, vh, ah, al);

    o_gemm<<<dim3(Hh / 128, Mm / 128), 128, gemm_smem>>>(ah, al, wgt + 3 * WSZ, out);
}

// round 10
// speedup vs baseline: 2.2502x; 1.4387x over previous
#include <cuda_runtime.h>
#include <cuda_bf16.h>
#include <cuda_fp16.h>
#include <math.h>
#include <stdint.h>

#define Bb 2
#define Ss 2048
#define Hh 2048
#define NHh 16
#define HDd 128
#define Mm (Bb*Ss)
#define GK 2048
#define GCH1 64
#define GNCH1 (GK/GCH1)    // 32

// ---------------- scratch ----------------
__device__ float g_cos[Ss*64];
__device__ float g_sin[Ss*64];
__device__ __half g_ah[(size_t)Mm*GK];         // activation (fp16)
__device__ __half g_w[4][(size_t)Hh*GK];       // weights fp16 (q,k,v,o)
// flash fp16 operands
__device__ __half g_qh[(size_t)Bb*NHh*Ss*HDd];
__device__ __half g_ql[(size_t)Bb*NHh*Ss*HDd];
__device__ __half g_kh[(size_t)Bb*NHh*Ss*HDd];
__device__ __half g_vh[(size_t)Bb*NHh*Ss*HDd];

// ---------------- PTX helpers ----------------
__device__ __forceinline__ uint32_t smem_u32(const void* p) {
    uint32_t a;
    asm("{ .reg .u64 t; cvta.to.shared.u64 t, %1; cvt.u32.u64 %0, t; }" : "=r"(a) : "l"(p));
    return a;
}
#define CP_ASYNC16(sa, gp) \
    asm volatile("cp.async.cg.shared.global [%0], [%1], 16;" :: "r"(sa), "l"(gp) : "memory")
#define CP_COMMIT() asm volatile("cp.async.commit_group;" ::: "memory")
#define CP_WAIT0()  asm volatile("cp.async.wait_group 0;" ::: "memory")
#define CP_WAIT1()  asm volatile("cp.async.wait_group 1;" ::: "memory")

__device__ __forceinline__ void ldsm_x4(uint32_t* r, uint32_t addr) {
    asm volatile("ldmatrix.sync.aligned.m8n8.x4.shared.b16 {%0,%1,%2,%3}, [%4];"
        : "=r"(r[0]), "=r"(r[1]), "=r"(r[2]), "=r"(r[3]) : "r"(addr));
}
__device__ __forceinline__ void ldsm_x4_t(uint32_t* r, uint32_t addr) {
    asm volatile("ldmatrix.sync.aligned.m8n8.x4.trans.shared.b16 {%0,%1,%2,%3}, [%4];"
        : "=r"(r[0]), "=r"(r[1]), "=r"(r[2]), "=r"(r[3]) : "r"(addr));
}
__device__ __forceinline__ void mma16816h(float* d, const uint32_t* a, const uint32_t* b) {
    asm volatile("mma.sync.aligned.m16n8k16.row.col.f32.f16.f16.f32 "
        "{%0,%1,%2,%3}, {%4,%5,%6,%7}, {%8,%9}, {%0,%1,%2,%3};"
        : "+f"(d[0]), "+f"(d[1]), "+f"(d[2]), "+f"(d[3])
        : "r"(a[0]), "r"(a[1]), "r"(a[2]), "r"(a[3]), "r"(b[0]), "r"(b[1]));
}
#define SWZ128(o) ((o) ^ (((o) >> 3) & 0x70))

// ---------------- fp16 activation convert ----------------
__global__ void convert_act(const float* __restrict__ X, __half* __restrict__ Y, int n)
{
    int idx = blockIdx.x * blockDim.x + threadIdx.x;
    if (idx >= n) return;
    Y[idx] = __float2half_rn(X[idx]);
}

// ---------------- all-4 weight fp16 converts in one launch ----------------
__global__ void convert_w4(const float* __restrict__ w0, const float* __restrict__ w1,
                           const float* __restrict__ w2, const float* __restrict__ w3,
                           __half* __restrict__ H)
{
    int idx = blockIdx.x * blockDim.x + threadIdx.x;
    const int t = blockIdx.y;
    if (idx >= Hh * Hh) return;
    const float* W = (t == 0) ? w0 : (t == 1) ? w1 : (t == 2) ? w2 : w3;
    H[(size_t)t * Hh * GK + idx] = __float2half_rn(W[idx]);
}

// ---------------- RoPE tables ----------------
__global__ void rope_tables_kernel()
{
    int idx = blockIdx.x * blockDim.x + threadIdx.x;
    if (idx >= Ss * 64) return;
    int s = idx >> 6;
    int d = idx & 63;
    float invf = (float)pow(10000.0, -(double)d * (1.0 / 64.0));
    float ang = (float)s * invf;
    float c, sn;
    sincosf(ang, &sn, &c);
    g_cos[idx] = c;
    g_sin[idx] = sn;
}

// ---------------- 1-product fp16 GEMM mainloop (CTA 128x128, 4 warps, 3-stage) --
// K-chunk 64 (128B rows, SW128). C = fp16(A)*fp16(B)^T, fp32 accum.
#define STG1 32768u

#define GEMM_LOAD_STAGE1(ci, st) do {                                               \
    const int _k0 = (ci) * GCH1;                                                    \
    const uint32_t _bs = sb + (uint32_t)(st) * STG1;                                \
    _Pragma("unroll")                                                               \
    for (int _i = 0; _i < 8; _i++) {                                                \
        int _idx = tid + 128 * _i;                                                  \
        int _r = _idx >> 3;                                                         \
        int _cb = (_idx & 7) * 16;                                                  \
        CP_ASYNC16(_bs + SWZ128(_r * 128 + _cb),                                    \
                   Ah + (size_t)(m0 + _r) * GK + _k0 + (_cb >> 1));                 \
    }                                                                               \
    _Pragma("unroll")                                                               \
    for (int _i = 0; _i < 8; _i++) {                                                \
        int _idx = tid + 128 * _i;                                                  \
        int _r = _idx >> 3;                                                         \
        int _cb = (_idx & 7) * 16;                                                  \
        CP_ASYNC16(_bs + 16384u + SWZ128(_r * 128 + _cb),                           \
                   Bw + (size_t)(n0 + _r) * GK + _k0 + (_cb >> 1));                 \
    }                                                                               \
    CP_COMMIT();                                                                    \
} while (0)

#define GEMM_MAINLOOP1()                                                            \
    const uint32_t a_half = (uint32_t)((lane >> 4) * 16);                           \
    const uint32_t a_xor = (uint32_t)((lane & 7) * 16);                             \
    uint32_t aRow[4];                                                               \
    _Pragma("unroll")                                                               \
    for (int mi = 0; mi < 4; mi++)                                                  \
        aRow[mi] = (uint32_t)((wm * 64 + mi * 16 + (lane & 15)) * 128);             \
    const int b_lrow = (lane & 7) + ((lane >> 4) << 3);                             \
    const uint32_t b_half = (uint32_t)(((lane >> 3) & 1) * 16);                     \
    const uint32_t b_xor = (uint32_t)((lane & 7) * 16);                             \
    uint32_t bRow[4];                                                               \
    _Pragma("unroll")                                                               \
    for (int nt = 0; nt < 4; nt++)                                                  \
        bRow[nt] = (uint32_t)((wn * 64 + nt * 16 + b_lrow) * 128);                  \
    GEMM_LOAD_STAGE1(0, 0);                                                         \
    GEMM_LOAD_STAGE1(1, 1);                                                         \
    for (int c = 0; c < GNCH1; c++) {                                               \
        if (c + 2 < GNCH1) CP_WAIT1(); else CP_WAIT0();                             \
        __syncthreads();                                                            \
        if (c + 2 < GNCH1) GEMM_LOAD_STAGE1(c + 2, (c + 2) % 3);                    \
        const uint32_t bs = sb + (uint32_t)(c % 3) * STG1;                          \
        _Pragma("unroll")                                                           \
        for (int kk = 0; kk < 4; kk++) {                                            \
            const uint32_t acol = ((uint32_t)(kk * 32) + a_half) ^ a_xor;           \
            const uint32_t bcol = ((uint32_t)(kk * 32) + b_half) ^ b_xor;           \
            uint32_t a4[4][4], b4[4][4];                                            \
            _Pragma("unroll")                                                       \
            for (int mi = 0; mi < 4; mi++)                                          \
                ldsm_x4(a4[mi], bs + aRow[mi] + acol);                              \
            _Pragma("unroll")                                                       \
            for (int nt = 0; nt < 4; nt++)                                          \
                ldsm_x4(b4[nt], bs + 16384u + bRow[nt] + bcol);                     \
            _Pragma("unroll")                                                       \
            for (int mi = 0; mi < 4; mi++)                                          \
                _Pragma("unroll")                                                   \
                for (int nt = 0; nt < 4; nt++) {                                    \
                    mma16816h(acc[mi][2 * nt],     a4[mi], b4[nt]);                 \
                    mma16816h(acc[mi][2 * nt + 1], a4[mi], b4[nt] + 2);             \
                }                                                                   \
        }                                                                           \
    }

// ---------------- fused QKV GEMM: blockIdx.z = 0(Q rope), 1(K rope), 2(V) -------
__global__ __launch_bounds__(128, 2) void qkv_gemm(const __half* __restrict__ Ah,
                                                   const __half* __restrict__ Wg,
                                                   __half* __restrict__ qh,
                                                   __half* __restrict__ ql,
                                                   __half* __restrict__ kh,
                                                   __half* __restrict__ vh)
{
    extern __shared__ char smem[];
    const uint32_t sb = smem_u32(smem);
    const int tid = threadIdx.x;
    const int wid = tid >> 5;
    const int lane = tid & 31;
    const int n0 = blockIdx.x * 128;
    const int m0 = blockIdx.y * 128;
    const int z = blockIdx.z;
    const int wm = wid & 1;
    const int wn = wid >> 1;
    const __half* Bw = Wg + (size_t)z * Hh * GK;

    float acc[4][8][4];
#pragma unroll
    for (int mi = 0; mi < 4; mi++)
#pragma unroll
        for (int ni = 0; ni < 8; ni++)
#pragma unroll
            for (int q = 0; q < 4; q++) acc[mi][ni][q] = 0.f;

    GEMM_MAINLOOP1();

    const int er = lane >> 2;
    const int ec = (lane & 3) * 2;

    if (z == 2) {
        // V: direct fp16 head scatter
#pragma unroll
        for (int mi = 0; mi < 4; mi++) {
#pragma unroll
            for (int ni = 0; ni < 8; ni++) {
                const int m = m0 + wm * 64 + mi * 16 + er;
                const int n = n0 + wn * 64 + ni * 8 + ec;
                const int b_ = m >> 11;
                const int s_ = m & (Ss - 1);
                const int h_ = n >> 7;
                const int d_ = n & (HDd - 1);
                const size_t o0 = (((size_t)b_ * NHh + h_) * Ss + s_) * HDd + d_;
                *(__half2*)(vh + o0) = __floats2half2_rn(acc[mi][ni][0], acc[mi][ni][1]);
                *(__half2*)(vh + o0 + 8 * HDd) = __floats2half2_rn(acc[mi][ni][2], acc[mi][ni][3]);
            }
        }
        return;
    }

    // Q/K: stage fp32 tile through smem, apply RoPE, emit fp16 (hi/lo for Q)
    __syncthreads();
    float* Cs = (float*)smem;   // [128][130]
#pragma unroll
    for (int mi = 0; mi < 4; mi++) {
#pragma unroll
        for (int ni = 0; ni < 8; ni++) {
            const int rr = wm * 64 + mi * 16 + er;
            const int cc = wn * 64 + ni * 8 + ec;
            Cs[rr * 130 + cc]           = acc[mi][ni][0];
            Cs[rr * 130 + cc + 1]       = acc[mi][ni][1];
            Cs[(rr + 8) * 130 + cc]     = acc[mi][ni][2];
            Cs[(rr + 8) * 130 + cc + 1] = acc[mi][ni][3];
        }
    }
    __syncthreads();

    const int d = tid & 63;
    const int rg = tid >> 6;
    const int b_ = blockIdx.y >> 4;
    const int h_ = blockIdx.x;
    const int s0 = m0 & (Ss - 1);
    const float rsc = 0.08838834764831845f;

    for (int rr = rg * 64; rr < rg * 64 + 64; rr++) {
        const int s = s0 + rr;
        const float x1 = Cs[rr * 130 + d];
        const float x2 = Cs[rr * 130 + d + 64];
        const float c = g_cos[s * 64 + d];
        const float sn = g_sin[s * 64 + d];
        float r1 = x1 * c - x2 * sn;
        float r2 = x2 * c + x1 * sn;
        const size_t ob = (((size_t)b_ * NHh + h_) * Ss + s) * HDd + d;
        if (z == 0) {
            r1 *= rsc; r2 *= rsc;
            const __half h1 = __float2half_rn(r1);
            const __half h2 = __float2half_rn(r2);
            qh[ob] = h1;
            qh[ob + 64] = h2;
            ql[ob] = __float2half_rn(r1 - __half2float(h1));
            ql[ob + 64] = __float2half_rn(r2 - __half2float(h2));
        } else {
            kh[ob] = __float2half_rn(r1);
            kh[ob + 64] = __float2half_rn(r2);
        }
    }
}

// ---------------- O GEMM: fp32 row-major out ----------------
__global__ __launch_bounds__(128, 2) void o_gemm(const __half* __restrict__ Ah,
                                                 const __half* __restrict__ Bw,
                                                 float* __restrict__ C)
{
    extern __shared__ char smem[];
    const uint32_t sb = smem_u32(smem);
    const int tid = threadIdx.x;
    const int wid = tid >> 5;
    const int lane = tid & 31;
    const int n0 = blockIdx.x * 128;
    const int m0 = blockIdx.y * 128;
    const int wm = wid & 1;
    const int wn = wid >> 1;

    float acc[4][8][4];
#pragma unroll
    for (int mi = 0; mi < 4; mi++)
#pragma unroll
        for (int ni = 0; ni < 8; ni++)
#pragma unroll
            for (int q = 0; q < 4; q++) acc[mi][ni][q] = 0.f;

    GEMM_MAINLOOP1();

    const int er = lane >> 2;
    const int ec = (lane & 3) * 2;
#pragma unroll
    for (int mi = 0; mi < 4; mi++) {
#pragma unroll
        for (int ni = 0; ni < 8; ni++) {
            const int m = m0 + wm * 64 + mi * 16 + er;
            const int n = n0 + wn * 64 + ni * 8 + ec;
            *(float2*)(C + (size_t)m * Hh + n) =
                make_float2(acc[mi][ni][0], acc[mi][ni][1]);
            *(float2*)(C + (size_t)(m + 8) * Hh + n) =
                make_float2(acc[mi][ni][2], acc[mi][ni][3]);
        }
    }
}

// ---------------- fp16 HMMA causal flash attention, BM=128, BN=64 ---------------
#define QsO 0u
#define KsO 65536u
#define VsO 98304u
#define FLASH_SMEM 131072

__global__ __launch_bounds__(256, 1) void flash_mma(
    const __half* __restrict__ qh, const __half* __restrict__ ql,
    const __half* __restrict__ kh, const __half* __restrict__ vh,
    __half* __restrict__ Oh)
{
    extern __shared__ char smem[];
    const uint32_t sb = smem_u32(smem);
    const int tid = threadIdx.x;
    const int lane = tid & 31;
    const int w = tid >> 5;
    const int qb = (gridDim.x - 1) - blockIdx.x;
    const int bh = blockIdx.y;
    const int b = bh >> 4, h = bh & 15;
    const int qlo = qb * 128;
    const int wr = w * 16;

#pragma unroll
    for (int i = 0; i < 16; i++) {
        int idx = tid + 256 * i;
        int row = idx >> 5;
        int off = (idx & 31) * 16;
        const __half* src = (off < 256)
            ? qh + ((size_t)bh * Ss + qlo + row) * HDd + (off >> 1)
            : ql + ((size_t)bh * Ss + qlo + row) * HDd + ((off - 256) >> 1);
        uint32_t dst = sb + QsO + row * 512 + (off & ~127) + ((off & 127) ^ ((row & 7) << 4));
        CP_ASYNC16(dst, src);
    }
    CP_COMMIT();

#define LOAD_KV(kb_, s_) do {                                                        \
    const int _klo = (kb_) * 64;                                                     \
    _Pragma("unroll")                                                                \
    for (int _i = 0; _i < 4; _i++) {                                                 \
        int _idx = tid + 256 * _i;                                                   \
        int _row = _idx >> 4;                                                        \
        int _off = (_idx & 15) * 16;                                                 \
        const __half* _src = kh + ((size_t)bh * Ss + _klo + _row) * HDd + (_off >> 1); \
        uint32_t _dst = sb + KsO + (s_) * 16384u + _row * 256 + (_off & ~127)        \
                        + ((_off & 127) ^ ((_row & 7) << 4));                        \
        CP_ASYNC16(_dst, _src);                                                      \
    }                                                                                \
    _Pragma("unroll")                                                                \
    for (int _i = 0; _i < 4; _i++) {                                                 \
        int _idx = tid + 256 * _i;                                                   \
        int _row = _idx >> 4;                                                        \
        int _off = (_idx & 15) * 16;                                                 \
        const __half* _src = vh + ((size_t)bh * Ss + _klo + _row) * HDd + (_off >> 1); \
        uint32_t _dst = sb + VsO + (s_) * 16384u + _row * 256 + (_off & ~127)        \
                        + ((_off & 127) ^ ((_row & 7) << 4));                        \
        CP_ASYNC16(_dst, _src);                                                      \
    }                                                                                \
    CP_COMMIT();                                                                     \
} while (0)

    LOAD_KV(0, 0);

    const int a_row = wr + (lane & 15);
    const uint32_t a_base = sb + QsO + a_row * 512;
    const uint32_t a_half = (uint32_t)((lane >> 4) * 16);
    const uint32_t a_xor = (uint32_t)((a_row & 7) * 16);

    const int b_rowk = (lane & 7) + ((lane >> 4) << 3);
    const uint32_t b_halfk = (uint32_t)(((lane >> 3) & 1) * 16);
    const uint32_t b_xork = (uint32_t)((lane & 7) * 16);

    const int v_row = (lane & 7) + (((lane >> 3) & 1) << 3);
    const uint32_t v_half = (uint32_t)((lane >> 4) * 16);
    const uint32_t v_xor = (uint32_t)((lane & 7) * 16);

    float oacc[16][4];
#pragma unroll
    for (int i = 0; i < 16; i++)
#pragma unroll
        for (int q = 0; q < 4; q++) oacc[i][q] = 0.f;
    float m0 = -1e30f, m1 = -1e30f, l0 = 0.f, l1 = 0.f;

    const int row_q0 = qlo + wr + (lane >> 2);
    const int nkb = 2 * qb + 2;

    for (int kb = 0; kb < nkb; kb++) {
        const int klo = kb * 64;
        CP_WAIT0();
        __syncthreads();
        if (kb + 1 < nkb) LOAD_KV(kb + 1, (kb + 1) & 1);

        const bool warp_skip = (klo > qlo + wr + 15);
        if (!warp_skip) {
            const uint32_t kbase = sb + KsO + (uint32_t)(kb & 1) * 16384u;
            const uint32_t vbase = sb + VsO + (uint32_t)(kb & 1) * 16384u;

            float sacc[8][4];
#pragma unroll
            for (int i = 0; i < 8; i++)
#pragma unroll
                for (int q = 0; q < 4; q++) sacc[i][q] = 0.f;

#pragma unroll
            for (int kk = 0; kk < 8; kk++) {
                const uint32_t acol = ((uint32_t)((kk & 3) * 32) + a_half) ^ a_xor;
                const uint32_t achunk = (uint32_t)((kk >> 2) * 128);
                uint32_t ahi[4], alo[4];
                ldsm_x4(ahi, a_base + achunk + acol);
                ldsm_x4(alo, a_base + 256u + achunk + acol);
                const uint32_t bcol = ((uint32_t)((kk & 3) * 32) + b_halfk) ^ b_xork;
#pragma unroll
                for (int g = 0; g < 4; g++) {
                    uint32_t bk[4];
                    ldsm_x4(bk, kbase + (uint32_t)((g * 16 + b_rowk) * 256) + achunk + bcol);
                    mma16816h(sacc[2 * g],     ahi, bk);
                    mma16816h(sacc[2 * g + 1], ahi, bk + 2);
                    mma16816h(sacc[2 * g],     alo, bk);
                    mma16816h(sacc[2 * g + 1], alo, bk + 2);
                }
            }

            if (klo + 63 > qlo + wr) {
#pragma unroll
                for (int nt = 0; nt < 8; nt++) {
                    const int cb = klo + nt * 8 + (lane & 3) * 2;
                    if (cb     > row_q0)     sacc[nt][0] = -1e30f;
                    if (cb + 1 > row_q0)     sacc[nt][1] = -1e30f;
                    if (cb     > row_q0 + 8) sacc[nt][2] = -1e30f;
                    if (cb + 1 > row_q0 + 8) sacc[nt][3] = -1e30f;
                }
            }

            float nm0 = -1e30f, nm1 = -1e30f;
#pragma unroll
            for (int nt = 0; nt < 8; nt++) {
                nm0 = fmaxf(nm0, fmaxf(sacc[nt][0], sacc[nt][1]));
                nm1 = fmaxf(nm1, fmaxf(sacc[nt][2], sacc[nt][3]));
            }
            nm0 = fmaxf(nm0, __shfl_xor_sync(0xffffffffu, nm0, 1));
            nm0 = fmaxf(nm0, __shfl_xor_sync(0xffffffffu, nm0, 2));
            nm1 = fmaxf(nm1, __shfl_xor_sync(0xffffffffu, nm1, 1));
            nm1 = fmaxf(nm1, __shfl_xor_sync(0xffffffffu, nm1, 2));
            nm0 = fmaxf(m0, nm0);
            nm1 = fmaxf(m1, nm1);
            const float alpha0 = __expf(m0 - nm0);
            const float alpha1 = __expf(m1 - nm1);
            m0 = nm0; m1 = nm1;

            uint32_t phi[8][2], plo[8][2];
            float s0 = 0.f, s1 = 0.f;
#pragma unroll
            for (int nt = 0; nt < 8; nt++) {
                float p00 = __expf(sacc[nt][0] - m0);
                float p01 = __expf(sacc[nt][1] - m0);
                float p10 = __expf(sacc[nt][2] - m1);
                float p11 = __expf(sacc[nt][3] - m1);
                s0 += p00 + p01;
                s1 += p10 + p11;
                __half2 h0 = __floats2half2_rn(p00, p01);
                __half2 h1 = __floats2half2_rn(p10, p11);
                phi[nt][0] = *(uint32_t*)&h0;
                phi[nt][1] = *(uint32_t*)&h1;
                float2 f0 = __half22float2(h0);
                float2 f1 = __half22float2(h1);
                __half2 e0 = __floats2half2_rn(p00 - f0.x, p01 - f0.y);
                __half2 e1 = __floats2half2_rn(p10 - f1.x, p11 - f1.y);
                plo[nt][0] = *(uint32_t*)&e0;
                plo[nt][1] = *(uint32_t*)&e1;
            }
            s0 += __shfl_xor_sync(0xffffffffu, s0, 1);
            s0 += __shfl_xor_sync(0xffffffffu, s0, 2);
            s1 += __shfl_xor_sync(0xffffffffu, s1, 1);
            s1 += __shfl_xor_sync(0xffffffffu, s1, 2);
            l0 = l0 * alpha0 + s0;
            l1 = l1 * alpha1 + s1;
#pragma unroll
            for (int dt = 0; dt < 16; dt++) {
                oacc[dt][0] *= alpha0; oacc[dt][1] *= alpha0;
                oacc[dt][2] *= alpha1; oacc[dt][3] *= alpha1;
            }

#pragma unroll
            for (int jt = 0; jt < 4; jt++) {
                uint32_t ah[4] = { phi[2 * jt][0], phi[2 * jt][1],
                                   phi[2 * jt + 1][0], phi[2 * jt + 1][1] };
                uint32_t al[4] = { plo[2 * jt][0], plo[2 * jt][1],
                                   plo[2 * jt + 1][0], plo[2 * jt + 1][1] };
                const uint32_t vrow = (uint32_t)((jt * 16 + v_row) * 256);
#pragma unroll
                for (int g = 0; g < 8; g++) {
                    const uint32_t colb = (uint32_t)(g * 32) + v_half;
                    const uint32_t voff = vrow + (colb & ~127u) + ((colb & 127u) ^ v_xor);
                    uint32_t bv[4];
                    ldsm_x4_t(bv, vbase + voff);
                    mma16816h(oacc[2 * g],     ah, bv);
                    mma16816h(oacc[2 * g + 1], ah, bv + 2);
                    mma16816h(oacc[2 * g],     al, bv);
                    mma16816h(oacc[2 * g + 1], al, bv + 2);
                }
            }
        }
        __syncthreads();
    }

    // epilogue: normalize + fp16 activation out
    const float inv0 = 1.f / l0;
    const float inv1 = 1.f / l1;
    const int col0 = h * HDd + (lane & 3) * 2;
    const size_t base0 = ((size_t)b * Ss + row_q0) * Hh + col0;
    const size_t base1 = ((size_t)b * Ss + row_q0 + 8) * Hh + col0;
#pragma unroll
    for (int dt = 0; dt < 16; dt++) {
        *(__half2*)(Oh + base0 + dt * 8) =
            __floats2half2_rn(oacc[dt][0] * inv0, oacc[dt][1] * inv0);
        *(__half2*)(Oh + base1 + dt * 8) =
            __floats2half2_rn(oacc[dt][2] * inv1, oacc[dt][3] * inv1);
    }
#undef LOAD_KV
}

// ---------------- launch ----------------
extern "C" void kernel_launch(void* const* d_in, const int* in_sizes, int n_in,
                              void* d_out, int out_size)
{
    (void)in_sizes; (void)n_in; (void)out_size;
    const float* hs = (const float*)d_in[0];
    const float* qw = (const float*)d_in[1];
    const float* kw = (const float*)d_in[2];
    const float* vw = (const float*)d_in[3];
    const float* ow = (const float*)d_in[4];
    float* out = (float*)d_out;

    __half *ah, *wgt, *qh, *ql, *kh, *vh;
    cudaGetSymbolAddress((void**)&ah, g_ah);
    cudaGetSymbolAddress((void**)&wgt, g_w);
    cudaGetSymbolAddress((void**)&qh, g_qh);
    cudaGetSymbolAddress((void**)&ql, g_ql);
    cudaGetSymbolAddress((void**)&kh, g_kh);
    cudaGetSymbolAddress((void**)&vh, g_vh);
    const size_t WSZ = (size_t)Hh * GK;

    const int gemm_smem = 98304;  // 3 stages x 32KB; also covers 66.5KB rope tile
    cudaFuncSetAttribute(qkv_gemm, cudaFuncAttributeMaxDynamicSharedMemorySize, gemm_smem);
    cudaFuncSetAttribute(o_gemm, cudaFuncAttributeMaxDynamicSharedMemorySize, gemm_smem);
    cudaFuncSetAttribute(flash_mma, cudaFuncAttributeMaxDynamicSharedMemorySize, FLASH_SMEM);

    const int actN = Mm * Hh;
    const int wN = Hh * Hh;

    convert_act<<<(actN + 255) / 256, 256>>>(hs, ah, actN);
    convert_w4<<<dim3((wN + 255) / 256, 4), 256>>>(qw, kw, vw, ow, wgt);
    rope_tables_kernel<<<(Ss * 64 + 255) / 256, 256>>>();

    // fused Q/K/V projections (+ RoPE + fp16 splits in epilogue)
    qkv_gemm<<<dim3(Hh / 128, Mm / 128, 3), 128, gemm_smem>>>(ah, wgt, qh, ql, kh, vh);

    // flash overwrites ah with the attention-output activation (fp16)
    flash_mma<<<dim3(Ss / 128, Bb * NHh), 256, FLASH_SMEM>>>(qh, ql, kh, vh, ah);

    o_gemm<<<dim3(Hh / 128, Mm / 128), 128, gemm_smem>>>(ah, wgt + 3 * WSZ, out);
}

// round 11
// speedup vs baseline: 2.4927x; 1.1078x over previous
#include <cuda_runtime.h>
#include <cuda_bf16.h>
#include <cuda_fp16.h>
#include <math.h>
#include <stdint.h>

#define Bb 2
#define Ss 2048
#define Hh 2048
#define NHh 16
#define HDd 128
#define Mm (Bb*Ss)
#define GK 2048
#define GCH1 64
#define GNCH1 (GK/GCH1)    // 32

// ---------------- scratch ----------------
__device__ float g_cos[Ss*64];
__device__ float g_sin[Ss*64];
__device__ __half g_ah[(size_t)Mm*GK];         // activation (fp16)
__device__ __half g_w[4][(size_t)Hh*GK];       // weights fp16 (q,k,v,o)
// flash fp16 operands
__device__ __half g_qh[(size_t)Bb*NHh*Ss*HDd];
__device__ __half g_kh[(size_t)Bb*NHh*Ss*HDd];
__device__ __half g_vh[(size_t)Bb*NHh*Ss*HDd];

// ---------------- PTX helpers ----------------
__device__ __forceinline__ uint32_t smem_u32(const void* p) {
    uint32_t a;
    asm("{ .reg .u64 t; cvta.to.shared.u64 t, %1; cvt.u32.u64 %0, t; }" : "=r"(a) : "l"(p));
    return a;
}
#define CP_ASYNC16(sa, gp) \
    asm volatile("cp.async.cg.shared.global [%0], [%1], 16;" :: "r"(sa), "l"(gp) : "memory")
#define CP_COMMIT() asm volatile("cp.async.commit_group;" ::: "memory")
#define CP_WAIT0()  asm volatile("cp.async.wait_group 0;" ::: "memory")
#define CP_WAIT1()  asm volatile("cp.async.wait_group 1;" ::: "memory")

__device__ __forceinline__ void ldsm_x4(uint32_t* r, uint32_t addr) {
    asm volatile("ldmatrix.sync.aligned.m8n8.x4.shared.b16 {%0,%1,%2,%3}, [%4];"
        : "=r"(r[0]), "=r"(r[1]), "=r"(r[2]), "=r"(r[3]) : "r"(addr));
}
__device__ __forceinline__ void ldsm_x4_t(uint32_t* r, uint32_t addr) {
    asm volatile("ldmatrix.sync.aligned.m8n8.x4.trans.shared.b16 {%0,%1,%2,%3}, [%4];"
        : "=r"(r[0]), "=r"(r[1]), "=r"(r[2]), "=r"(r[3]) : "r"(addr));
}
__device__ __forceinline__ void mma16816h(float* d, const uint32_t* a, const uint32_t* b) {
    asm volatile("mma.sync.aligned.m16n8k16.row.col.f32.f16.f16.f32 "
        "{%0,%1,%2,%3}, {%4,%5,%6,%7}, {%8,%9}, {%0,%1,%2,%3};"
        : "+f"(d[0]), "+f"(d[1]), "+f"(d[2]), "+f"(d[3])
        : "r"(a[0]), "r"(a[1]), "r"(a[2]), "r"(a[3]), "r"(b[0]), "r"(b[1]));
}
#define SWZ128(o) ((o) ^ (((o) >> 3) & 0x70))

// ---------------- single prep kernel: act convert + 4 weight converts + rope ----
#define ACTN (Mm*Hh)            // 8388608
#define WN   (Hh*Hh)            // 4194304
#define PREP_TOTAL (ACTN + 4*WN + Ss*64)

__global__ void prep_kernel(const float* __restrict__ hs,
                            const float* __restrict__ w0, const float* __restrict__ w1,
                            const float* __restrict__ w2, const float* __restrict__ w3,
                            __half* __restrict__ A, __half* __restrict__ H)
{
    int idx = blockIdx.x * blockDim.x + threadIdx.x;
    if (idx < ACTN) {
        A[idx] = __float2half_rn(hs[idx]);
        return;
    }
    idx -= ACTN;
    if (idx < 4 * WN) {
        const int t = idx >> 22;          // / WN
        const int j = idx & (WN - 1);
        const float* W = (t == 0) ? w0 : (t == 1) ? w1 : (t == 2) ? w2 : w3;
        H[(size_t)t * WN + j] = __float2half_rn(W[j]);
        return;
    }
    idx -= 4 * WN;
    if (idx < Ss * 64) {
        int s = idx >> 6;
        int d = idx & 63;
        float invf = (float)pow(10000.0, -(double)d * (1.0 / 64.0));
        float ang = (float)s * invf;
        float c, sn;
        sincosf(ang, &sn, &c);
        g_cos[idx] = c;
        g_sin[idx] = sn;
    }
}

// ---------------- 1-product fp16 GEMM mainloop (CTA 128x128, 4 warps, 3-stage) --
#define STG1 32768u

#define GEMM_LOAD_STAGE1(ci, st) do {                                               \
    const int _k0 = (ci) * GCH1;                                                    \
    const uint32_t _bs = sb + (uint32_t)(st) * STG1;                                \
    _Pragma("unroll")                                                               \
    for (int _i = 0; _i < 8; _i++) {                                                \
        int _idx = tid + 128 * _i;                                                  \
        int _r = _idx >> 3;                                                         \
        int _cb = (_idx & 7) * 16;                                                  \
        CP_ASYNC16(_bs + SWZ128(_r * 128 + _cb),                                    \
                   Ah + (size_t)(m0 + _r) * GK + _k0 + (_cb >> 1));                 \
    }                                                                               \
    _Pragma("unroll")                                                               \
    for (int _i = 0; _i < 8; _i++) {                                                \
        int _idx = tid + 128 * _i;                                                  \
        int _r = _idx >> 3;                                                         \
        int _cb = (_idx & 7) * 16;                                                  \
        CP_ASYNC16(_bs + 16384u + SWZ128(_r * 128 + _cb),                           \
                   Bw + (size_t)(n0 + _r) * GK + _k0 + (_cb >> 1));                 \
    }                                                                               \
    CP_COMMIT();                                                                    \
} while (0)

#define GEMM_MAINLOOP1()                                                            \
    const uint32_t a_half = (uint32_t)((lane >> 4) * 16);                           \
    const uint32_t a_xor = (uint32_t)((lane & 7) * 16);                             \
    uint32_t aRow[4];                                                               \
    _Pragma("unroll")                                                               \
    for (int mi = 0; mi < 4; mi++)                                                  \
        aRow[mi] = (uint32_t)((wm * 64 + mi * 16 + (lane & 15)) * 128);             \
    const int b_lrow = (lane & 7) + ((lane >> 4) << 3);                             \
    const uint32_t b_half = (uint32_t)(((lane >> 3) & 1) * 16);                     \
    const uint32_t b_xor = (uint32_t)((lane & 7) * 16);                             \
    uint32_t bRow[4];                                                               \
    _Pragma("unroll")                                                               \
    for (int nt = 0; nt < 4; nt++)                                                  \
        bRow[nt] = (uint32_t)((wn * 64 + nt * 16 + b_lrow) * 128);                  \
    GEMM_LOAD_STAGE1(0, 0);                                                         \
    GEMM_LOAD_STAGE1(1, 1);                                                         \
    for (int c = 0; c < GNCH1; c++) {                                               \
        if (c + 2 < GNCH1) CP_WAIT1(); else CP_WAIT0();                             \
        __syncthreads();                                                            \
        if (c + 2 < GNCH1) GEMM_LOAD_STAGE1(c + 2, (c + 2) % 3);                    \
        const uint32_t bs = sb + (uint32_t)(c % 3) * STG1;                          \
        _Pragma("unroll")                                                           \
        for (int kk = 0; kk < 4; kk++) {                                            \
            const uint32_t acol = ((uint32_t)(kk * 32) + a_half) ^ a_xor;           \
            const uint32_t bcol = ((uint32_t)(kk * 32) + b_half) ^ b_xor;           \
            uint32_t a4[4][4], b4[4][4];                                            \
            _Pragma("unroll")                                                       \
            for (int mi = 0; mi < 4; mi++)                                          \
                ldsm_x4(a4[mi], bs + aRow[mi] + acol);                              \
            _Pragma("unroll")                                                       \
            for (int nt = 0; nt < 4; nt++)                                          \
                ldsm_x4(b4[nt], bs + 16384u + bRow[nt] + bcol);                     \
            _Pragma("unroll")                                                       \
            for (int mi = 0; mi < 4; mi++)                                          \
                _Pragma("unroll")                                                   \
                for (int nt = 0; nt < 4; nt++) {                                    \
                    mma16816h(acc[mi][2 * nt],     a4[mi], b4[nt]);                 \
                    mma16816h(acc[mi][2 * nt + 1], a4[mi], b4[nt] + 2);             \
                }                                                                   \
        }                                                                           \
    }

// ---------------- fused QKV GEMM: blockIdx.z = 0(Q rope), 1(K rope), 2(V) -------
__global__ __launch_bounds__(128, 2) void qkv_gemm(const __half* __restrict__ Ah,
                                                   const __half* __restrict__ Wg,
                                                   __half* __restrict__ qh,
                                                   __half* __restrict__ kh,
                                                   __half* __restrict__ vh)
{
    extern __shared__ char smem[];
    const uint32_t sb = smem_u32(smem);
    const int tid = threadIdx.x;
    const int wid = tid >> 5;
    const int lane = tid & 31;
    const int n0 = blockIdx.x * 128;
    const int m0 = blockIdx.y * 128;
    const int z = blockIdx.z;
    const int wm = wid & 1;
    const int wn = wid >> 1;
    const __half* Bw = Wg + (size_t)z * Hh * GK;

    float acc[4][8][4];
#pragma unroll
    for (int mi = 0; mi < 4; mi++)
#pragma unroll
        for (int ni = 0; ni < 8; ni++)
#pragma unroll
            for (int q = 0; q < 4; q++) acc[mi][ni][q] = 0.f;

    GEMM_MAINLOOP1();

    const int er = lane >> 2;
    const int ec = (lane & 3) * 2;

    if (z == 2) {
        // V: direct fp16 head scatter
#pragma unroll
        for (int mi = 0; mi < 4; mi++) {
#pragma unroll
            for (int ni = 0; ni < 8; ni++) {
                const int m = m0 + wm * 64 + mi * 16 + er;
                const int n = n0 + wn * 64 + ni * 8 + ec;
                const int b_ = m >> 11;
                const int s_ = m & (Ss - 1);
                const int h_ = n >> 7;
                const int d_ = n & (HDd - 1);
                const size_t o0 = (((size_t)b_ * NHh + h_) * Ss + s_) * HDd + d_;
                *(__half2*)(vh + o0) = __floats2half2_rn(acc[mi][ni][0], acc[mi][ni][1]);
                *(__half2*)(vh + o0 + 8 * HDd) = __floats2half2_rn(acc[mi][ni][2], acc[mi][ni][3]);
            }
        }
        return;
    }

    // Q/K: stage fp32 tile through smem, apply RoPE, emit fp16
    __syncthreads();
    float* Cs = (float*)smem;   // [128][130]
#pragma unroll
    for (int mi = 0; mi < 4; mi++) {
#pragma unroll
        for (int ni = 0; ni < 8; ni++) {
            const int rr = wm * 64 + mi * 16 + er;
            const int cc = wn * 64 + ni * 8 + ec;
            Cs[rr * 130 + cc]           = acc[mi][ni][0];
            Cs[rr * 130 + cc + 1]       = acc[mi][ni][1];
            Cs[(rr + 8) * 130 + cc]     = acc[mi][ni][2];
            Cs[(rr + 8) * 130 + cc + 1] = acc[mi][ni][3];
        }
    }
    __syncthreads();

    const int d = tid & 63;
    const int rg = tid >> 6;
    const int b_ = blockIdx.y >> 4;
    const int h_ = blockIdx.x;
    const int s0 = m0 & (Ss - 1);
    const float rsc = 0.08838834764831845f;

    for (int rr = rg * 64; rr < rg * 64 + 64; rr++) {
        const int s = s0 + rr;
        const float x1 = Cs[rr * 130 + d];
        const float x2 = Cs[rr * 130 + d + 64];
        const float c = g_cos[s * 64 + d];
        const float sn = g_sin[s * 64 + d];
        float r1 = x1 * c - x2 * sn;
        float r2 = x2 * c + x1 * sn;
        const size_t ob = (((size_t)b_ * NHh + h_) * Ss + s) * HDd + d;
        if (z == 0) {
            qh[ob]      = __float2half_rn(r1 * rsc);
            qh[ob + 64] = __float2half_rn(r2 * rsc);
        } else {
            kh[ob]      = __float2half_rn(r1);
            kh[ob + 64] = __float2half_rn(r2);
        }
    }
}

// ---------------- O GEMM: fp32 row-major out ----------------
__global__ __launch_bounds__(128, 2) void o_gemm(const __half* __restrict__ Ah,
                                                 const __half* __restrict__ Bw,
                                                 float* __restrict__ C)
{
    extern __shared__ char smem[];
    const uint32_t sb = smem_u32(smem);
    const int tid = threadIdx.x;
    const int wid = tid >> 5;
    const int lane = tid & 31;
    const int n0 = blockIdx.x * 128;
    const int m0 = blockIdx.y * 128;
    const int wm = wid & 1;
    const int wn = wid >> 1;

    float acc[4][8][4];
#pragma unroll
    for (int mi = 0; mi < 4; mi++)
#pragma unroll
        for (int ni = 0; ni < 8; ni++)
#pragma unroll
            for (int q = 0; q < 4; q++) acc[mi][ni][q] = 0.f;

    GEMM_MAINLOOP1();

    const int er = lane >> 2;
    const int ec = (lane & 3) * 2;
#pragma unroll
    for (int mi = 0; mi < 4; mi++) {
#pragma unroll
        for (int ni = 0; ni < 8; ni++) {
            const int m = m0 + wm * 64 + mi * 16 + er;
            const int n = n0 + wn * 64 + ni * 8 + ec;
            *(float2*)(C + (size_t)m * Hh + n) =
                make_float2(acc[mi][ni][0], acc[mi][ni][1]);
            *(float2*)(C + (size_t)(m + 8) * Hh + n) =
                make_float2(acc[mi][ni][2], acc[mi][ni][3]);
        }
    }
}

// ---------------- fp16 HMMA causal flash attention (1-product), BM=128, BN=64 ---
// Q single plane (256B rows), S = Q*K, O = P*V.
#define QsO 0u
#define KsO 32768u
#define VsO 65536u
#define FLASH_SMEM 98304

__global__ __launch_bounds__(256, 1) void flash_mma(
    const __half* __restrict__ qh, const __half* __restrict__ kh,
    const __half* __restrict__ vh, __half* __restrict__ Oh)
{
    extern __shared__ char smem[];
    const uint32_t sb = smem_u32(smem);
    const int tid = threadIdx.x;
    const int lane = tid & 31;
    const int w = tid >> 5;
    const int qb = (gridDim.x - 1) - blockIdx.x;
    const int bh = blockIdx.y;
    const int b = bh >> 4, h = bh & 15;
    const int qlo = qb * 128;
    const int wr = w * 16;

    // Q tile: 128 rows x 256B
#pragma unroll
    for (int i = 0; i < 8; i++) {
        int idx = tid + 256 * i;
        int row = idx >> 4;
        int off = (idx & 15) * 16;
        const __half* src = qh + ((size_t)bh * Ss + qlo + row) * HDd + (off >> 1);
        uint32_t dst = sb + QsO + row * 256 + (off & ~127) + ((off & 127) ^ ((row & 7) << 4));
        CP_ASYNC16(dst, src);
    }
    CP_COMMIT();

#define LOAD_KV(kb_, s_) do {                                                        \
    const int _klo = (kb_) * 64;                                                     \
    _Pragma("unroll")                                                                \
    for (int _i = 0; _i < 4; _i++) {                                                 \
        int _idx = tid + 256 * _i;                                                   \
        int _row = _idx >> 4;                                                        \
        int _off = (_idx & 15) * 16;                                                 \
        const __half* _src = kh + ((size_t)bh * Ss + _klo + _row) * HDd + (_off >> 1); \
        uint32_t _dst = sb + KsO + (s_) * 16384u + _row * 256 + (_off & ~127)        \
                        + ((_off & 127) ^ ((_row & 7) << 4));                        \
        CP_ASYNC16(_dst, _src);                                                      \
    }                                                                                \
    _Pragma("unroll")                                                                \
    for (int _i = 0; _i < 4; _i++) {                                                 \
        int _idx = tid + 256 * _i;                                                   \
        int _row = _idx >> 4;                                                        \
        int _off = (_idx & 15) * 16;                                                 \
        const __half* _src = vh + ((size_t)bh * Ss + _klo + _row) * HDd + (_off >> 1); \
        uint32_t _dst = sb + VsO + (s_) * 16384u + _row * 256 + (_off & ~127)        \
                        + ((_off & 127) ^ ((_row & 7) << 4));                        \
        CP_ASYNC16(_dst, _src);                                                      \
    }                                                                                \
    CP_COMMIT();                                                                     \
} while (0)

    LOAD_KV(0, 0);

    const int a_row = wr + (lane & 15);
    const uint32_t a_base = sb + QsO + a_row * 256;
    const uint32_t a_half = (uint32_t)((lane >> 4) * 16);
    const uint32_t a_xor = (uint32_t)((a_row & 7) * 16);

    const int b_rowk = (lane & 7) + ((lane >> 4) << 3);
    const uint32_t b_halfk = (uint32_t)(((lane >> 3) & 1) * 16);
    const uint32_t b_xork = (uint32_t)((lane & 7) * 16);

    const int v_row = (lane & 7) + (((lane >> 3) & 1) << 3);
    const uint32_t v_half = (uint32_t)((lane >> 4) * 16);
    const uint32_t v_xor = (uint32_t)((lane & 7) * 16);

    float oacc[16][4];
#pragma unroll
    for (int i = 0; i < 16; i++)
#pragma unroll
        for (int q = 0; q < 4; q++) oacc[i][q] = 0.f;
    float m0 = -1e30f, m1 = -1e30f, l0 = 0.f, l1 = 0.f;

    const int row_q0 = qlo + wr + (lane >> 2);
    const int nkb = 2 * qb + 2;

    for (int kb = 0; kb < nkb; kb++) {
        const int klo = kb * 64;
        CP_WAIT0();
        __syncthreads();
        if (kb + 1 < nkb) LOAD_KV(kb + 1, (kb + 1) & 1);

        const bool warp_skip = (klo > qlo + wr + 15);
        if (!warp_skip) {
            const uint32_t kbase = sb + KsO + (uint32_t)(kb & 1) * 16384u;
            const uint32_t vbase = sb + VsO + (uint32_t)(kb & 1) * 16384u;

            float sacc[8][4];
#pragma unroll
            for (int i = 0; i < 8; i++)
#pragma unroll
                for (int q = 0; q < 4; q++) sacc[i][q] = 0.f;

            // S = Q*K (1-product)
#pragma unroll
            for (int kk = 0; kk < 8; kk++) {
                const uint32_t acol = ((uint32_t)((kk & 3) * 32) + a_half) ^ a_xor;
                const uint32_t achunk = (uint32_t)((kk >> 2) * 128);
                uint32_t aq[4];
                ldsm_x4(aq, a_base + achunk + acol);
                const uint32_t bcol = ((uint32_t)((kk & 3) * 32) + b_halfk) ^ b_xork;
#pragma unroll
                for (int g = 0; g < 4; g++) {
                    uint32_t bk[4];
                    ldsm_x4(bk, kbase + (uint32_t)((g * 16 + b_rowk) * 256) + achunk + bcol);
                    mma16816h(sacc[2 * g],     aq, bk);
                    mma16816h(sacc[2 * g + 1], aq, bk + 2);
                }
            }

            if (klo + 63 > qlo + wr) {
#pragma unroll
                for (int nt = 0; nt < 8; nt++) {
                    const int cb = klo + nt * 8 + (lane & 3) * 2;
                    if (cb     > row_q0)     sacc[nt][0] = -1e30f;
                    if (cb + 1 > row_q0)     sacc[nt][1] = -1e30f;
                    if (cb     > row_q0 + 8) sacc[nt][2] = -1e30f;
                    if (cb + 1 > row_q0 + 8) sacc[nt][3] = -1e30f;
                }
            }

            float nm0 = -1e30f, nm1 = -1e30f;
#pragma unroll
            for (int nt = 0; nt < 8; nt++) {
                nm0 = fmaxf(nm0, fmaxf(sacc[nt][0], sacc[nt][1]));
                nm1 = fmaxf(nm1, fmaxf(sacc[nt][2], sacc[nt][3]));
            }
            nm0 = fmaxf(nm0, __shfl_xor_sync(0xffffffffu, nm0, 1));
            nm0 = fmaxf(nm0, __shfl_xor_sync(0xffffffffu, nm0, 2));
            nm1 = fmaxf(nm1, __shfl_xor_sync(0xffffffffu, nm1, 1));
            nm1 = fmaxf(nm1, __shfl_xor_sync(0xffffffffu, nm1, 2));
            nm0 = fmaxf(m0, nm0);
            nm1 = fmaxf(m1, nm1);
            const float alpha0 = __expf(m0 - nm0);
            const float alpha1 = __expf(m1 - nm1);
            m0 = nm0; m1 = nm1;

            uint32_t phi[8][2];
            float s0 = 0.f, s1 = 0.f;
#pragma unroll
            for (int nt = 0; nt < 8; nt++) {
                float p00 = __expf(sacc[nt][0] - m0);
                float p01 = __expf(sacc[nt][1] - m0);
                float p10 = __expf(sacc[nt][2] - m1);
                float p11 = __expf(sacc[nt][3] - m1);
                s0 += p00 + p01;
                s1 += p10 + p11;
                __half2 h0 = __floats2half2_rn(p00, p01);
                __half2 h1 = __floats2half2_rn(p10, p11);
                phi[nt][0] = *(uint32_t*)&h0;
                phi[nt][1] = *(uint32_t*)&h1;
            }
            s0 += __shfl_xor_sync(0xffffffffu, s0, 1);
            s0 += __shfl_xor_sync(0xffffffffu, s0, 2);
            s1 += __shfl_xor_sync(0xffffffffu, s1, 1);
            s1 += __shfl_xor_sync(0xffffffffu, s1, 2);
            l0 = l0 * alpha0 + s0;
            l1 = l1 * alpha1 + s1;
#pragma unroll
            for (int dt = 0; dt < 16; dt++) {
                oacc[dt][0] *= alpha0; oacc[dt][1] *= alpha0;
                oacc[dt][2] *= alpha1; oacc[dt][3] *= alpha1;
            }

            // O += P*V (1-product)
#pragma unroll
            for (int jt = 0; jt < 4; jt++) {
                uint32_t ap[4] = { phi[2 * jt][0], phi[2 * jt][1],
                                   phi[2 * jt + 1][0], phi[2 * jt + 1][1] };
                const uint32_t vrow = (uint32_t)((jt * 16 + v_row) * 256);
#pragma unroll
                for (int g = 0; g < 8; g++) {
                    const uint32_t colb = (uint32_t)(g * 32) + v_half;
                    const uint32_t voff = vrow + (colb & ~127u) + ((colb & 127u) ^ v_xor);
                    uint32_t bv[4];
                    ldsm_x4_t(bv, vbase + voff);
                    mma16816h(oacc[2 * g],     ap, bv);
                    mma16816h(oacc[2 * g + 1], ap, bv + 2);
                }
            }
        }
        __syncthreads();
    }

    // epilogue: normalize + fp16 activation out
    const float inv0 = 1.f / l0;
    const float inv1 = 1.f / l1;
    const int col0 = h * HDd + (lane & 3) * 2;
    const size_t base0 = ((size_t)b * Ss + row_q0) * Hh + col0;
    const size_t base1 = ((size_t)b * Ss + row_q0 + 8) * Hh + col0;
#pragma unroll
    for (int dt = 0; dt < 16; dt++) {
        *(__half2*)(Oh + base0 + dt * 8) =
            __floats2half2_rn(oacc[dt][0] * inv0, oacc[dt][1] * inv0);
        *(__half2*)(Oh + base1 + dt * 8) =
            __floats2half2_rn(oacc[dt][2] * inv1, oacc[dt][3] * inv1);
    }
#undef LOAD_KV
}

// ---------------- launch ----------------
extern "C" void kernel_launch(void* const* d_in, const int* in_sizes, int n_in,
                              void* d_out, int out_size)
{
    (void)in_sizes; (void)n_in; (void)out_size;
    const float* hs = (const float*)d_in[0];
    const float* qw = (const float*)d_in[1];
    const float* kw = (const float*)d_in[2];
    const float* vw = (const float*)d_in[3];
    const float* ow = (const float*)d_in[4];
    float* out = (float*)d_out;

    __half *ah, *wgt, *qh, *kh, *vh;
    cudaGetSymbolAddress((void**)&ah, g_ah);
    cudaGetSymbolAddress((void**)&wgt, g_w);
    cudaGetSymbolAddress((void**)&qh, g_qh);
    cudaGetSymbolAddress((void**)&kh, g_kh);
    cudaGetSymbolAddress((void**)&vh, g_vh);
    const size_t WSZ = (size_t)Hh * GK;

    const int gemm_smem = 98304;  // 3 stages x 32KB; also covers 66.5KB rope tile
    cudaFuncSetAttribute(qkv_gemm, cudaFuncAttributeMaxDynamicSharedMemorySize, gemm_smem);
    cudaFuncSetAttribute(o_gemm, cudaFuncAttributeMaxDynamicSharedMemorySize, gemm_smem);
    cudaFuncSetAttribute(flash_mma, cudaFuncAttributeMaxDynamicSharedMemorySize, FLASH_SMEM);

    prep_kernel<<<(PREP_TOTAL + 255) / 256, 256>>>(hs, qw, kw, vw, ow, ah, wgt);

    // fused Q/K/V projections (+ RoPE + fp16 convert in epilogue)
    qkv_gemm<<<dim3(Hh / 128, Mm / 128, 3), 128, gemm_smem>>>(ah, wgt, qh, kh, vh);

    // flash overwrites ah with the attention-output activation (fp16)
    flash_mma<<<dim3(Ss / 128, Bb * NHh), 256, FLASH_SMEM>>>(qh, kh, vh, ah);

    o_gemm<<<dim3(Hh / 128, Mm / 128), 128, gemm_smem>>>(ah, wgt + 3 * WSZ, out);
}